// round 1
// baseline (speedup 1.0000x reference)
#include <cuda_runtime.h>

#define Bb 16
#define Cc 128
#define Hh 128
#define Ww 128
#define Nn 16384          // Hh*Ww
#define SPLIT 32
#define KCHUNK 512        // Nn / SPLIT

// Scratch (static device globals; no allocation at runtime)
static __device__ float g_part[SPLIT][Bb][Cc][Cc];          // 32 MB split-K partials
static __device__ float g_A[Bb][Cc][Cc];                    // rowmax - Gram
static __device__ float g_att2[(size_t)Bb * Cc * Nn];       // 134 MB pre-conv tensor

// ---------------------------------------------------------------------------
// Kernel 1: split-K Gram partials. Block = (split sp, batch b).
// Computes partial G[b] += f[:,k0:k0+512] * f[:,k0:k0+512]^T  (128x128 out)
// ---------------------------------------------------------------------------
__global__ __launch_bounds__(256, 2)
void k_gram(const float* __restrict__ x) {
    const int b  = blockIdx.y;
    const int sp = blockIdx.x;
    const float* __restrict__ f = x + (size_t)b * Cc * Nn;
    const int kbase = sp * KCHUNK;

    __shared__ __align__(16) float sT[2][32][132];   // [kk][c], padded

    const int tid = threadIdx.x;
    const int ty = tid >> 4, tx = tid & 15;
    const int lr = tid >> 3;          // 0..31 (row group)
    const int lk = (tid & 7) << 2;    // 0,4,...,28 (k offset)

    float acc[8][8];
#pragma unroll
    for (int i = 0; i < 8; i++)
#pragma unroll
        for (int j = 0; j < 8; j++) acc[i][j] = 0.f;

    float4 v[4];
    // prologue: tile 0
#pragma unroll
    for (int p = 0; p < 4; p++)
        v[p] = *(const float4*)(f + (size_t)(lr + p * 32) * Nn + kbase + lk);
#pragma unroll
    for (int p = 0; p < 4; p++) {
        sT[0][lk + 0][lr + p * 32] = v[p].x;
        sT[0][lk + 1][lr + p * 32] = v[p].y;
        sT[0][lk + 2][lr + p * 32] = v[p].z;
        sT[0][lk + 3][lr + p * 32] = v[p].w;
    }
    __syncthreads();

    int buf = 0;
    const int NT = KCHUNK / 32;       // 16
    for (int kt = 0; kt < NT; kt++) {
        if (kt + 1 < NT) {
            const int k0 = kbase + (kt + 1) * 32 + lk;
#pragma unroll
            for (int p = 0; p < 4; p++)
                v[p] = *(const float4*)(f + (size_t)(lr + p * 32) * Nn + k0);
        }
#pragma unroll
        for (int kk = 0; kk < 32; kk++) {
            float a[8], bb[8];
            *(float4*)&a[0]  = *(const float4*)&sT[buf][kk][ty * 8];
            *(float4*)&a[4]  = *(const float4*)&sT[buf][kk][ty * 8 + 4];
            *(float4*)&bb[0] = *(const float4*)&sT[buf][kk][tx * 8];
            *(float4*)&bb[4] = *(const float4*)&sT[buf][kk][tx * 8 + 4];
#pragma unroll
            for (int i = 0; i < 8; i++)
#pragma unroll
                for (int j = 0; j < 8; j++)
                    acc[i][j] = fmaf(a[i], bb[j], acc[i][j]);
        }
        if (kt + 1 < NT) {
            const int nb = buf ^ 1;
#pragma unroll
            for (int p = 0; p < 4; p++) {
                sT[nb][lk + 0][lr + p * 32] = v[p].x;
                sT[nb][lk + 1][lr + p * 32] = v[p].y;
                sT[nb][lk + 2][lr + p * 32] = v[p].z;
                sT[nb][lk + 3][lr + p * 32] = v[p].w;
            }
            __syncthreads();
            buf = nb;
        }
    }

    float* gp = &g_part[sp][b][0][0];
#pragma unroll
    for (int i = 0; i < 8; i++) {
        *(float4*)(gp + (ty * 8 + i) * Cc + tx * 8) =
            make_float4(acc[i][0], acc[i][1], acc[i][2], acc[i][3]);
        *(float4*)(gp + (ty * 8 + i) * Cc + tx * 8 + 4) =
            make_float4(acc[i][4], acc[i][5], acc[i][6], acc[i][7]);
    }
}

// ---------------------------------------------------------------------------
// Kernel 2: reduce split-K partials, row-max, A = max - G. Block = (c, b).
// ---------------------------------------------------------------------------
__global__ __launch_bounds__(128)
void k_reduce() {
    const int c = blockIdx.x, b = blockIdx.y;
    const int d = threadIdx.x;     // 0..127
    float s = 0.f;
#pragma unroll 8
    for (int sp = 0; sp < SPLIT; sp++) s += g_part[sp][b][c][d];

    float m = s;
#pragma unroll
    for (int o = 16; o; o >>= 1) m = fmaxf(m, __shfl_xor_sync(0xffffffffu, m, o));
    __shared__ float wm[4];
    if ((d & 31) == 0) wm[d >> 5] = m;
    __syncthreads();
    m = fmaxf(fmaxf(wm[0], wm[1]), fmaxf(wm[2], wm[3]));

    g_A[b][c][d] = m - s;
}

// ---------------------------------------------------------------------------
// Kernel 3: atten2 = A * f  (per batch 128 x 16384, K = 128). Block = (ntile, b).
// ---------------------------------------------------------------------------
__global__ __launch_bounds__(256, 2)
void k_gemm2(const float* __restrict__ x) {
    const int b  = blockIdx.y;
    const int n0 = blockIdx.x * 128;
    const float* __restrict__ f = x + (size_t)b * Cc * Nn;

    __shared__ __align__(16) float sA[32][132];   // [dd][c] transposed A tile
    __shared__ __align__(16) float sF[32][128];   // [dd][n]

    const int tid = threadIdx.x;
    const int ty = tid >> 4, tx = tid & 15;

    float acc[8][8];
#pragma unroll
    for (int i = 0; i < 8; i++)
#pragma unroll
        for (int j = 0; j < 8; j++) acc[i][j] = 0.f;

    for (int kt = 0; kt < 4; kt++) {
        if (kt) __syncthreads();
        const int d0 = kt * 32;
        {   // A tile (transposed store)
            const int lr = tid >> 3, lk = (tid & 7) << 2;
#pragma unroll
            for (int p = 0; p < 4; p++) {
                float4 u = *(const float4*)&g_A[b][lr + p * 32][d0 + lk];
                sA[lk + 0][lr + p * 32] = u.x;
                sA[lk + 1][lr + p * 32] = u.y;
                sA[lk + 2][lr + p * 32] = u.z;
                sA[lk + 3][lr + p * 32] = u.w;
            }
        }
        {   // F tile (direct)
            const int dd = tid >> 5;              // 0..7
            const int n4 = (tid & 31) << 2;       // 0..124
#pragma unroll
            for (int p = 0; p < 4; p++)
                *(float4*)&sF[dd + p * 8][n4] =
                    *(const float4*)(f + (size_t)(d0 + dd + p * 8) * Nn + n0 + n4);
        }
        __syncthreads();
#pragma unroll
        for (int kk = 0; kk < 32; kk++) {
            float a[8], bb[8];
            *(float4*)&a[0]  = *(const float4*)&sA[kk][ty * 8];
            *(float4*)&a[4]  = *(const float4*)&sA[kk][ty * 8 + 4];
            *(float4*)&bb[0] = *(const float4*)&sF[kk][tx * 8];
            *(float4*)&bb[4] = *(const float4*)&sF[kk][tx * 8 + 4];
#pragma unroll
            for (int i = 0; i < 8; i++)
#pragma unroll
                for (int j = 0; j < 8; j++)
                    acc[i][j] = fmaf(a[i], bb[j], acc[i][j]);
        }
    }

    float* op = g_att2 + (size_t)b * Cc * Nn;
#pragma unroll
    for (int i = 0; i < 8; i++) {
        *(float4*)(op + (size_t)(ty * 8 + i) * Nn + n0 + tx * 8) =
            make_float4(acc[i][0], acc[i][1], acc[i][2], acc[i][3]);
        *(float4*)(op + (size_t)(ty * 8 + i) * Nn + n0 + tx * 8 + 4) =
            make_float4(acc[i][4], acc[i][5], acc[i][6], acc[i][7]);
    }
}

// ---------------------------------------------------------------------------
// Kernel 4: depthwise 3x3 conv (pad=1) + bias + softmax over W + final outputs.
// Block = (c, b), one 128x128 plane in padded smem, one warp per softmax row.
// d_out layout: [out (B*C*H*W) | atten (B*C*H*W)]
// ---------------------------------------------------------------------------
__global__ __launch_bounds__(256)
void k_conv(const float* __restrict__ x, const float* __restrict__ dwW,
            const float* __restrict__ dwB, const float* __restrict__ gamma,
            float* __restrict__ out) {
    extern __shared__ float sm[];   // [130][132] padded plane
    const int c = blockIdx.x, b = blockIdx.y;
    const int tid = threadIdx.x;

    for (int i = tid; i < 130 * 132; i += 256) sm[i] = 0.f;
    __syncthreads();

    const float* __restrict__ pl = g_att2 + ((size_t)b * Cc + c) * Nn;
    for (int idx = tid << 2; idx < Nn; idx += 1024) {
        float4 u = *(const float4*)(pl + idx);
        const int h = idx >> 7, w = idx & 127;
        float* r = sm + (h + 1) * 132 + (w + 1);
        r[0] = u.x; r[1] = u.y; r[2] = u.z; r[3] = u.w;
    }

    float w9[9];
#pragma unroll
    for (int i = 0; i < 9; i++) w9[i] = dwW[c * 9 + i];
    const float bz = dwB[c];
    const float gm = gamma[0];
    __syncthreads();

    const int warp = tid >> 5, lane = tid & 31;
    const float* __restrict__ xp = x + ((size_t)b * Cc + c) * Nn;
    float* __restrict__ op = out + ((size_t)b * Cc + c) * Nn;
    float* __restrict__ ap = out + (size_t)Bb * Cc * Nn + ((size_t)b * Cc + c) * Nn;

    for (int h = warp; h < Hh; h += 8) {
        const int wb = lane << 2;   // 0..124
        // padded input rows h..h+2, cols wb..wb+7 (need wb..wb+5)
        float r0[8], r1[8], r2[8];
        {
            float4 a0 = *(const float4*)&sm[(h + 0) * 132 + wb];
            float4 a1 = *(const float4*)&sm[(h + 0) * 132 + wb + 4];
            r0[0]=a0.x; r0[1]=a0.y; r0[2]=a0.z; r0[3]=a0.w;
            r0[4]=a1.x; r0[5]=a1.y; r0[6]=a1.z; r0[7]=a1.w;
            float4 b0 = *(const float4*)&sm[(h + 1) * 132 + wb];
            float4 b1 = *(const float4*)&sm[(h + 1) * 132 + wb + 4];
            r1[0]=b0.x; r1[1]=b0.y; r1[2]=b0.z; r1[3]=b0.w;
            r1[4]=b1.x; r1[5]=b1.y; r1[6]=b1.z; r1[7]=b1.w;
            float4 c0 = *(const float4*)&sm[(h + 2) * 132 + wb];
            float4 c1 = *(const float4*)&sm[(h + 2) * 132 + wb + 4];
            r2[0]=c0.x; r2[1]=c0.y; r2[2]=c0.z; r2[3]=c0.w;
            r2[4]=c1.x; r2[5]=c1.y; r2[6]=c1.z; r2[7]=c1.w;
        }
        float v[4];
#pragma unroll
        for (int j = 0; j < 4; j++) {
            float s = bz;
            s = fmaf(r0[j],     w9[0], s);
            s = fmaf(r0[j + 1], w9[1], s);
            s = fmaf(r0[j + 2], w9[2], s);
            s = fmaf(r1[j],     w9[3], s);
            s = fmaf(r1[j + 1], w9[4], s);
            s = fmaf(r1[j + 2], w9[5], s);
            s = fmaf(r2[j],     w9[6], s);
            s = fmaf(r2[j + 1], w9[7], s);
            s = fmaf(r2[j + 2], w9[8], s);
            v[j] = s;
        }
        float mx = fmaxf(fmaxf(v[0], v[1]), fmaxf(v[2], v[3]));
#pragma unroll
        for (int o = 16; o; o >>= 1) mx = fmaxf(mx, __shfl_xor_sync(0xffffffffu, mx, o));
        float e[4]; float ssum = 0.f;
#pragma unroll
        for (int j = 0; j < 4; j++) { e[j] = __expf(v[j] - mx); ssum += e[j]; }
#pragma unroll
        for (int o = 16; o; o >>= 1) ssum += __shfl_xor_sync(0xffffffffu, ssum, o);
        const float inv = 1.0f / ssum;

        float4 xv = *(const float4*)(xp + h * Ww + wb);
        float4 av = make_float4(e[0] * inv, e[1] * inv, e[2] * inv, e[3] * inv);
        *(float4*)(ap + h * Ww + wb) = av;
        *(float4*)(op + h * Ww + wb) = make_float4(
            fmaf(gm, av.x, xv.x), fmaf(gm, av.y, xv.y),
            fmaf(gm, av.z, xv.z), fmaf(gm, av.w, xv.w));
    }
}

// ---------------------------------------------------------------------------
extern "C" void kernel_launch(void* const* d_in, const int* in_sizes, int n_in,
                              void* d_out, int out_size) {
    (void)in_sizes; (void)n_in; (void)out_size;
    const float* x    = (const float*)d_in[0];
    const float* dwW  = (const float*)d_in[1];
    const float* dwB  = (const float*)d_in[2];
    const float* gm   = (const float*)d_in[3];
    float* out = (float*)d_out;

    cudaFuncSetAttribute(k_conv, cudaFuncAttributeMaxDynamicSharedMemorySize,
                         130 * 132 * 4);

    k_gram  <<<dim3(SPLIT, Bb), 256>>>(x);
    k_reduce<<<dim3(Cc, Bb),   128>>>();
    k_gemm2 <<<dim3(Nn / 128, Bb), 256>>>(x);
    k_conv  <<<dim3(Cc, Bb),   256, 130 * 132 * 4>>>(x, dwW, dwB, gm, out);
}

// round 3
// speedup vs baseline: 1.4877x; 1.4877x over previous
#include <cuda_runtime.h>
#include <cuda_bf16.h>

#define Bb 16
#define Cc 128
#define Hh 128
#define Ww 128
#define Nn 16384          // Hh*Ww
#define SPLITG 8          // split-K for Gram
#define KCHUNK_G 2048     // Nn / SPLITG

// ---------------- scratch (static device globals) ----------------
static __device__ float g_part[SPLITG][Bb][Cc][Cc];         // 8 MB Gram split-K partials
static __device__ float g_A[Bb][Cc][Cc];                    // rowmax - Gram (fp32)
static __device__ __nv_bfloat16 g_Ah[Bb][Cc][Cc];           // A hi
static __device__ __nv_bfloat16 g_Al[Bb][Cc][Cc];           // A lo
static __device__ float g_att2[(size_t)Bb * Cc * Nn];       // 134 MB pre-conv tensor
static __device__ __nv_bfloat16 g_xh[(size_t)Bb * Cc * Nn]; // 67 MB x hi
static __device__ __nv_bfloat16 g_xl[(size_t)Bb * Cc * Nn]; // 67 MB x lo

// ---------------- mma / ldmatrix helpers (plain PTX, sm_80+) ----------------
__device__ __forceinline__ unsigned smem_u32(const void* p) {
    unsigned a;
    asm("{ .reg .u64 t; cvta.to.shared.u64 t, %1; cvt.u32.u64 %0, t; }"
        : "=r"(a) : "l"(p));
    return a;
}
__device__ __forceinline__ void ldsm4(unsigned* r, unsigned addr) {
    asm volatile("ldmatrix.sync.aligned.m8n8.x4.shared.b16 {%0,%1,%2,%3}, [%4];"
                 : "=r"(r[0]), "=r"(r[1]), "=r"(r[2]), "=r"(r[3]) : "r"(addr));
}
__device__ __forceinline__ void ldsm4t(unsigned* r, unsigned addr) {
    asm volatile("ldmatrix.sync.aligned.m8n8.x4.trans.shared.b16 {%0,%1,%2,%3}, [%4];"
                 : "=r"(r[0]), "=r"(r[1]), "=r"(r[2]), "=r"(r[3]) : "r"(addr));
}
__device__ __forceinline__ void mma16816(float* c, const unsigned* a, const unsigned* b) {
    asm volatile(
        "mma.sync.aligned.m16n8k16.row.col.f32.bf16.bf16.f32 "
        "{%0,%1,%2,%3}, {%4,%5,%6,%7}, {%8,%9}, {%0,%1,%2,%3};"
        : "+f"(c[0]), "+f"(c[1]), "+f"(c[2]), "+f"(c[3])
        : "r"(a[0]), "r"(a[1]), "r"(a[2]), "r"(a[3]), "r"(b[0]), "r"(b[1]));
}

// ---------------------------------------------------------------------------
// Kernel 0: fp32 -> bf16 hi/lo split of x
// ---------------------------------------------------------------------------
__global__ __launch_bounds__(256)
void k_convert(const float* __restrict__ x) {
    const size_t tot4 = (size_t)Bb * Cc * Nn / 4;
    for (size_t i = (size_t)blockIdx.x * blockDim.x + threadIdx.x; i < tot4;
         i += (size_t)gridDim.x * blockDim.x) {
        float4 v = ((const float4*)x)[i];
        __nv_bfloat16 h0 = __float2bfloat16_rn(v.x);
        __nv_bfloat16 h1 = __float2bfloat16_rn(v.y);
        __nv_bfloat16 h2 = __float2bfloat16_rn(v.z);
        __nv_bfloat16 h3 = __float2bfloat16_rn(v.w);
        __nv_bfloat16 l0 = __float2bfloat16_rn(v.x - __bfloat162float(h0));
        __nv_bfloat16 l1 = __float2bfloat16_rn(v.y - __bfloat162float(h1));
        __nv_bfloat16 l2 = __float2bfloat16_rn(v.z - __bfloat162float(h2));
        __nv_bfloat16 l3 = __float2bfloat16_rn(v.w - __bfloat162float(h3));
        ((__nv_bfloat162*)g_xh)[2 * i]     = __halves2bfloat162(h0, h1);
        ((__nv_bfloat162*)g_xh)[2 * i + 1] = __halves2bfloat162(h2, h3);
        ((__nv_bfloat162*)g_xl)[2 * i]     = __halves2bfloat162(l0, l1);
        ((__nv_bfloat162*)g_xl)[2 * i + 1] = __halves2bfloat162(l2, l3);
    }
}

// ---------------------------------------------------------------------------
// Kernel 1: Gram split-K partials via HMMA bf16 (hi/lo 3-pass).
// Block = (sp, b), 8 warps. Block tile M=128(c) x N=128(d), K-chunk = 64.
// Warp tile: 32(m) x 64(n).
// ---------------------------------------------------------------------------
__global__ __launch_bounds__(256)
void k_gram_mma() {
    __shared__ __align__(16) __nv_bfloat16 sH[128][72];   // 18.4 KB, stride 144B
    __shared__ __align__(16) __nv_bfloat16 sL[128][72];

    const int b  = blockIdx.y;
    const int sp = blockIdx.x;
    const int tid = threadIdx.x;
    const int wid = tid >> 5, lane = tid & 31;
    const int wm = wid & 3, wn = wid >> 2;     // warp row/col group

    const unsigned uH = smem_u32(&sH[0][0]);
    const unsigned uL = smem_u32(&sL[0][0]);

    float acc[2][8][4];
#pragma unroll
    for (int mi = 0; mi < 2; mi++)
#pragma unroll
        for (int nb = 0; nb < 8; nb++)
#pragma unroll
            for (int q = 0; q < 4; q++) acc[mi][nb][q] = 0.f;

    // fragment smem addresses (byte offsets inside the padded tiles)
    const int arow = wm * 32 + (lane & 15);
    const int acolq = (lane >> 4) * 8;
    const int brow = (lane & 7) + ((lane >> 4) & 1) * 8;
    const int bcolq = ((lane >> 3) & 1) * 8;

    const size_t kb0 = (size_t)sp * KCHUNK_G;
    const int NIT = KCHUNK_G / 64;   // 32

    for (int it = 0; it < NIT; it++) {
        const size_t kb = kb0 + (size_t)it * 64;
        __syncthreads();
        // stage 128 rows x 64 bf16 (hi & lo)
#pragma unroll
        for (int q = 0; q < 4; q++) {
            const int idx = tid + q * 256;        // 0..1023
            const int row = idx >> 3, c8 = idx & 7;
            const size_t src = (size_t)(b * Cc + row) * Nn + kb + c8 * 8;
            *(uint4*)&sH[row][c8 * 8] = *(const uint4*)(g_xh + src);
            *(uint4*)&sL[row][c8 * 8] = *(const uint4*)(g_xl + src);
        }
        __syncthreads();

#pragma unroll
        for (int kk = 0; kk < 4; kk++) {
            unsigned aH[2][4], aL[2][4];
#pragma unroll
            for (int mi = 0; mi < 2; mi++) {
                const unsigned ao =
                    (unsigned)(((arow + mi * 16) * 72 + kk * 16 + acolq) * 2);
                ldsm4(aH[mi], uH + ao);
                ldsm4(aL[mi], uL + ao);
            }
#pragma unroll
            for (int ni = 0; ni < 4; ni++) {
                unsigned bH[4], bL[4];
                const unsigned bo =
                    (unsigned)(((wn * 64 + ni * 16 + brow) * 72 + kk * 16 + bcolq) * 2);
                ldsm4(bH, uH + bo);
                ldsm4(bL, uL + bo);
#pragma unroll
                for (int mi = 0; mi < 2; mi++) {
                    mma16816(acc[mi][2 * ni],     aH[mi], &bH[0]);
                    mma16816(acc[mi][2 * ni],     aH[mi], &bL[0]);
                    mma16816(acc[mi][2 * ni],     aL[mi], &bH[0]);
                    mma16816(acc[mi][2 * ni + 1], aH[mi], &bH[2]);
                    mma16816(acc[mi][2 * ni + 1], aH[mi], &bL[2]);
                    mma16816(acc[mi][2 * ni + 1], aL[mi], &bH[2]);
                }
            }
        }
    }

    // epilogue: write partials
    float* gp = &g_part[sp][b][0][0];
#pragma unroll
    for (int mi = 0; mi < 2; mi++) {
        const int r0 = wm * 32 + mi * 16 + (lane >> 2);
#pragma unroll
        for (int nb = 0; nb < 8; nb++) {
            const int col = wn * 64 + nb * 8 + (lane & 3) * 2;
            *(float2*)(gp + (size_t)r0 * Cc + col) =
                make_float2(acc[mi][nb][0], acc[mi][nb][1]);
            *(float2*)(gp + (size_t)(r0 + 8) * Cc + col) =
                make_float2(acc[mi][nb][2], acc[mi][nb][3]);
        }
    }
}

// ---------------------------------------------------------------------------
// Kernel 2: reduce split-K partials, row-max, A = max - G, + bf16 hi/lo of A.
// ---------------------------------------------------------------------------
__global__ __launch_bounds__(128)
void k_reduce() {
    const int c = blockIdx.x, b = blockIdx.y;
    const int d = threadIdx.x;
    float s = 0.f;
#pragma unroll
    for (int sp = 0; sp < SPLITG; sp++) s += g_part[sp][b][c][d];

    float m = s;
#pragma unroll
    for (int o = 16; o; o >>= 1) m = fmaxf(m, __shfl_xor_sync(0xffffffffu, m, o));
    __shared__ float wm[4];
    if ((d & 31) == 0) wm[d >> 5] = m;
    __syncthreads();
    m = fmaxf(fmaxf(wm[0], wm[1]), fmaxf(wm[2], wm[3]));

    const float a = m - s;
    g_A[b][c][d] = a;
    __nv_bfloat16 h = __float2bfloat16_rn(a);
    g_Ah[b][c][d] = h;
    g_Al[b][c][d] = __float2bfloat16_rn(a - __bfloat162float(h));
}

// ---------------------------------------------------------------------------
// Kernel 3: atten2 = A * f via HMMA bf16 (hi/lo 3-pass).
// Block = (ntile, b), 8 warps. Tile M=128(c) x N=128(n), K=128(d), chunk 32.
// B fragments via ldmatrix.trans from k-major f tile.
// ---------------------------------------------------------------------------
__global__ __launch_bounds__(256)
void k_gemm2_mma() {
    __shared__ __align__(16) __nv_bfloat16 sAh[128][40];   // 10.2 KB
    __shared__ __align__(16) __nv_bfloat16 sAl[128][40];
    __shared__ __align__(16) __nv_bfloat16 sBh[32][136];   // 8.7 KB
    __shared__ __align__(16) __nv_bfloat16 sBl[32][136];

    const int b  = blockIdx.y;
    const int n0 = blockIdx.x * 128;
    const int tid = threadIdx.x;
    const int wid = tid >> 5, lane = tid & 31;
    const int wm = wid & 3, wn = wid >> 2;

    const unsigned uAh = smem_u32(&sAh[0][0]);
    const unsigned uAl = smem_u32(&sAl[0][0]);
    const unsigned uBh = smem_u32(&sBh[0][0]);
    const unsigned uBl = smem_u32(&sBl[0][0]);

    float acc[2][8][4];
#pragma unroll
    for (int mi = 0; mi < 2; mi++)
#pragma unroll
        for (int nb = 0; nb < 8; nb++)
#pragma unroll
            for (int q = 0; q < 4; q++) acc[mi][nb][q] = 0.f;

    const int arow = wm * 32 + (lane & 15);
    const int acolq = (lane >> 4) * 8;
    const int btrow = lane & 15;            // k-row within chunk tile
    const int btcolq = (lane >> 4) * 8;     // n offset

    for (int kt = 0; kt < 4; kt++) {
        const int k0 = kt * 32;
        __syncthreads();
        {   // stage A chunk: 128 c x 32 k  (512 uint4 per array)
#pragma unroll
            for (int q = 0; q < 2; q++) {
                const int idx = tid + q * 256;   // 0..511
                const int row = idx >> 2, c8 = idx & 3;
                *(uint4*)&sAh[row][c8 * 8] = *(const uint4*)&g_Ah[b][row][k0 + c8 * 8];
                *(uint4*)&sAl[row][c8 * 8] = *(const uint4*)&g_Al[b][row][k0 + c8 * 8];
            }
            // stage B chunk: 32 k x 128 n
#pragma unroll
            for (int q = 0; q < 2; q++) {
                const int idx = tid + q * 256;   // 0..511
                const int row = idx >> 4, c8 = idx & 15;
                const size_t src = (size_t)(b * Cc + k0 + row) * Nn + n0 + c8 * 8;
                *(uint4*)&sBh[row][c8 * 8] = *(const uint4*)(g_xh + src);
                *(uint4*)&sBl[row][c8 * 8] = *(const uint4*)(g_xl + src);
            }
        }
        __syncthreads();

#pragma unroll
        for (int kk = 0; kk < 2; kk++) {
            unsigned aH[2][4], aL[2][4];
#pragma unroll
            for (int mi = 0; mi < 2; mi++) {
                const unsigned ao =
                    (unsigned)(((arow + mi * 16) * 40 + kk * 16 + acolq) * 2);
                ldsm4(aH[mi], uAh + ao);
                ldsm4(aL[mi], uAl + ao);
            }
#pragma unroll
            for (int ni = 0; ni < 4; ni++) {
                unsigned bH[4], bL[4];
                const unsigned bo = (unsigned)(
                    ((kk * 16 + btrow) * 136 + wn * 64 + ni * 16 + btcolq) * 2);
                ldsm4t(bH, uBh + bo);
                ldsm4t(bL, uBl + bo);
#pragma unroll
                for (int mi = 0; mi < 2; mi++) {
                    mma16816(acc[mi][2 * ni],     aH[mi], &bH[0]);
                    mma16816(acc[mi][2 * ni],     aH[mi], &bL[0]);
                    mma16816(acc[mi][2 * ni],     aL[mi], &bH[0]);
                    mma16816(acc[mi][2 * ni + 1], aH[mi], &bH[2]);
                    mma16816(acc[mi][2 * ni + 1], aH[mi], &bL[2]);
                    mma16816(acc[mi][2 * ni + 1], aL[mi], &bH[2]);
                }
            }
        }
    }

    float* op = g_att2 + (size_t)b * Cc * Nn;
#pragma unroll
    for (int mi = 0; mi < 2; mi++) {
        const int r0 = wm * 32 + mi * 16 + (lane >> 2);
#pragma unroll
        for (int nb = 0; nb < 8; nb++) {
            const int col = n0 + wn * 64 + nb * 8 + (lane & 3) * 2;
            *(float2*)(op + (size_t)r0 * Nn + col) =
                make_float2(acc[mi][nb][0], acc[mi][nb][1]);
            *(float2*)(op + (size_t)(r0 + 8) * Nn + col) =
                make_float2(acc[mi][nb][2], acc[mi][nb][3]);
        }
    }
}

// ---------------------------------------------------------------------------
// Kernel 4: depthwise 3x3 conv + bias + softmax(W) + outputs.
// Block = (c, b, half): 64 output rows, 66-row halo in smem.
// ---------------------------------------------------------------------------
__global__ __launch_bounds__(256)
void k_conv(const float* __restrict__ x, const float* __restrict__ dwW,
            const float* __restrict__ dwB, const float* __restrict__ gamma,
            float* __restrict__ out) {
    __shared__ float sm[66 * 132];
    const int c = blockIdx.x, b = blockIdx.y;
    const int r0 = blockIdx.z * 64;
    const int tid = threadIdx.x;

    for (int i = tid; i < 66 * 132; i += 256) sm[i] = 0.f;
    __syncthreads();

    const float* __restrict__ pl = g_att2 + ((size_t)b * Cc + c) * Nn;
    for (int idx4 = tid; idx4 < 66 * 32; idx4 += 256) {
        const int i = idx4 >> 5, w4 = (idx4 & 31) << 2;
        const int gr = r0 - 1 + i;
        if (gr >= 0 && gr < Hh) {
            float4 u = *(const float4*)(pl + gr * Ww + w4);
            float* rp = sm + i * 132 + 1 + w4;
            rp[0] = u.x; rp[1] = u.y; rp[2] = u.z; rp[3] = u.w;
        }
    }

    float w9[9];
#pragma unroll
    for (int i = 0; i < 9; i++) w9[i] = dwW[c * 9 + i];
    const float bz = dwB[c];
    const float gm = gamma[0];
    __syncthreads();

    const int warp = tid >> 5, lane = tid & 31;
    const float* __restrict__ xp = x + ((size_t)b * Cc + c) * Nn;
    float* __restrict__ op = out + ((size_t)b * Cc + c) * Nn;
    float* __restrict__ ap = out + (size_t)Bb * Cc * Nn + ((size_t)b * Cc + c) * Nn;

    for (int hh = warp; hh < 64; hh += 8) {
        const int h = r0 + hh;
        const int li = hh + 1;
        const int wb = lane << 2;
        float r0v[8], r1v[8], r2v[8];
        {
            float4 a0 = *(const float4*)&sm[(li - 1) * 132 + wb];
            float4 a1 = *(const float4*)&sm[(li - 1) * 132 + wb + 4];
            r0v[0]=a0.x; r0v[1]=a0.y; r0v[2]=a0.z; r0v[3]=a0.w;
            r0v[4]=a1.x; r0v[5]=a1.y; r0v[6]=a1.z; r0v[7]=a1.w;
            float4 b0 = *(const float4*)&sm[(li + 0) * 132 + wb];
            float4 b1 = *(const float4*)&sm[(li + 0) * 132 + wb + 4];
            r1v[0]=b0.x; r1v[1]=b0.y; r1v[2]=b0.z; r1v[3]=b0.w;
            r1v[4]=b1.x; r1v[5]=b1.y; r1v[6]=b1.z; r1v[7]=b1.w;
            float4 c0 = *(const float4*)&sm[(li + 1) * 132 + wb];
            float4 c1 = *(const float4*)&sm[(li + 1) * 132 + wb + 4];
            r2v[0]=c0.x; r2v[1]=c0.y; r2v[2]=c0.z; r2v[3]=c0.w;
            r2v[4]=c1.x; r2v[5]=c1.y; r2v[6]=c1.z; r2v[7]=c1.w;
        }
        float v[4];
#pragma unroll
        for (int j = 0; j < 4; j++) {
            float s = bz;
            s = fmaf(r0v[j],     w9[0], s);
            s = fmaf(r0v[j + 1], w9[1], s);
            s = fmaf(r0v[j + 2], w9[2], s);
            s = fmaf(r1v[j],     w9[3], s);
            s = fmaf(r1v[j + 1], w9[4], s);
            s = fmaf(r1v[j + 2], w9[5], s);
            s = fmaf(r2v[j],     w9[6], s);
            s = fmaf(r2v[j + 1], w9[7], s);
            s = fmaf(r2v[j + 2], w9[8], s);
            v[j] = s;
        }
        float mx = fmaxf(fmaxf(v[0], v[1]), fmaxf(v[2], v[3]));
#pragma unroll
        for (int o = 16; o; o >>= 1) mx = fmaxf(mx, __shfl_xor_sync(0xffffffffu, mx, o));
        float e[4]; float ssum = 0.f;
#pragma unroll
        for (int j = 0; j < 4; j++) { e[j] = __expf(v[j] - mx); ssum += e[j]; }
#pragma unroll
        for (int o = 16; o; o >>= 1) ssum += __shfl_xor_sync(0xffffffffu, ssum, o);
        const float inv = 1.0f / ssum;

        float4 xv = *(const float4*)(xp + h * Ww + wb);
        float4 av = make_float4(e[0] * inv, e[1] * inv, e[2] * inv, e[3] * inv);
        *(float4*)(ap + h * Ww + wb) = av;
        *(float4*)(op + h * Ww + wb) = make_float4(
            fmaf(gm, av.x, xv.x), fmaf(gm, av.y, xv.y),
            fmaf(gm, av.z, xv.z), fmaf(gm, av.w, xv.w));
    }
}

// ---------------------------------------------------------------------------
extern "C" void kernel_launch(void* const* d_in, const int* in_sizes, int n_in,
                              void* d_out, int out_size) {
    (void)in_sizes; (void)n_in; (void)out_size;
    const float* x    = (const float*)d_in[0];
    const float* dwW  = (const float*)d_in[1];
    const float* dwB  = (const float*)d_in[2];
    const float* gm   = (const float*)d_in[3];
    float* out = (float*)d_out;

    k_convert  <<<8192, 256>>>(x);
    k_gram_mma <<<dim3(SPLITG, Bb), 256>>>();
    k_reduce   <<<dim3(Cc, Bb), 128>>>();
    k_gemm2_mma<<<dim3(Nn / 128, Bb), 256>>>();
    k_conv     <<<dim3(Cc, Bb, 2), 256>>>(x, dwW, dwB, gm, out);
}

// round 4
// speedup vs baseline: 1.5780x; 1.0607x over previous
#include <cuda_runtime.h>
#include <cuda_bf16.h>

#define Bb 16
#define Cc 128
#define Hh 128
#define Ww 128
#define Nn 16384          // Hh*Ww
#define SPLITG 8          // split-K for Gram
#define KCHUNK_G 2048     // Nn / SPLITG

// ---------------- scratch (static device globals) ----------------
static __device__ float g_part[SPLITG][Bb][Cc][Cc];         // 8 MB Gram split-K partials
static __device__ __nv_bfloat16 g_Gh[Bb][Cc][Cc];           // G hi
static __device__ __nv_bfloat16 g_Gl[Bb][Cc][Cc];           // G lo
static __device__ float g_m[Bb][Cc];                        // row max of G
static __device__ float g_S[Bb][Nn];                        // column sums of f (fp32 exact)
static __device__ float g_att2[(size_t)Bb * Cc * Nn];       // 134 MB pre-conv tensor

// ---------------- mma / ldmatrix helpers (plain PTX, sm_80+) ----------------
__device__ __forceinline__ unsigned smem_u32(const void* p) {
    unsigned a;
    asm("{ .reg .u64 t; cvta.to.shared.u64 t, %1; cvt.u32.u64 %0, t; }"
        : "=r"(a) : "l"(p));
    return a;
}
__device__ __forceinline__ void ldsm4(unsigned* r, unsigned addr) {
    asm volatile("ldmatrix.sync.aligned.m8n8.x4.shared.b16 {%0,%1,%2,%3}, [%4];"
                 : "=r"(r[0]), "=r"(r[1]), "=r"(r[2]), "=r"(r[3]) : "r"(addr));
}
__device__ __forceinline__ void ldsm4t(unsigned* r, unsigned addr) {
    asm volatile("ldmatrix.sync.aligned.m8n8.x4.trans.shared.b16 {%0,%1,%2,%3}, [%4];"
                 : "=r"(r[0]), "=r"(r[1]), "=r"(r[2]), "=r"(r[3]) : "r"(addr));
}
__device__ __forceinline__ void mma16816(float* c, const unsigned* a, const unsigned* b) {
    asm volatile(
        "mma.sync.aligned.m16n8k16.row.col.f32.bf16.bf16.f32 "
        "{%0,%1,%2,%3}, {%4,%5,%6,%7}, {%8,%9}, {%0,%1,%2,%3};"
        : "+f"(c[0]), "+f"(c[1]), "+f"(c[2]), "+f"(c[3])
        : "r"(a[0]), "r"(a[1]), "r"(a[2]), "r"(a[3]), "r"(b[0]), "r"(b[1]));
}

// split 8 fp32 -> 8 bf16 hi + 8 bf16 lo (packed as uint4 each)
__device__ __forceinline__ void split8(const float4 v0, const float4 v1,
                                       uint4& h, uint4& l) {
    __nv_bfloat162 h0 = __floats2bfloat162_rn(v0.x, v0.y);
    __nv_bfloat162 h1 = __floats2bfloat162_rn(v0.z, v0.w);
    __nv_bfloat162 h2 = __floats2bfloat162_rn(v1.x, v1.y);
    __nv_bfloat162 h3 = __floats2bfloat162_rn(v1.z, v1.w);
    unsigned b0 = *(unsigned*)&h0, b1 = *(unsigned*)&h1;
    unsigned b2 = *(unsigned*)&h2, b3 = *(unsigned*)&h3;
    // low half = first arg (low 16 bits); bf16 -> f32 = shift/mask trick
    float f0x = __uint_as_float(b0 << 16), f0y = __uint_as_float(b0 & 0xffff0000u);
    float f1x = __uint_as_float(b1 << 16), f1y = __uint_as_float(b1 & 0xffff0000u);
    float f2x = __uint_as_float(b2 << 16), f2y = __uint_as_float(b2 & 0xffff0000u);
    float f3x = __uint_as_float(b3 << 16), f3y = __uint_as_float(b3 & 0xffff0000u);
    __nv_bfloat162 l0 = __floats2bfloat162_rn(v0.x - f0x, v0.y - f0y);
    __nv_bfloat162 l1 = __floats2bfloat162_rn(v0.z - f1x, v0.w - f1y);
    __nv_bfloat162 l2 = __floats2bfloat162_rn(v1.x - f2x, v1.y - f2y);
    __nv_bfloat162 l3 = __floats2bfloat162_rn(v1.z - f3x, v1.w - f3y);
    h = make_uint4(b0, b1, b2, b3);
    l = make_uint4(*(unsigned*)&l0, *(unsigned*)&l1,
                   *(unsigned*)&l2, *(unsigned*)&l3);
}

// ---------------------------------------------------------------------------
// Kernel S: exact fp32 column sums S[b][n] = sum_c x[b][c][n]
// ---------------------------------------------------------------------------
__global__ __launch_bounds__(128)
void k_sums(const float* __restrict__ x) {
    const int b = blockIdx.y;
    const int n0 = blockIdx.x * 512;
    const int t = threadIdx.x;
    const float* base = x + (size_t)b * Cc * Nn + n0 + t * 4;
    float4 a0 = make_float4(0.f, 0.f, 0.f, 0.f), a1 = a0, a2 = a0, a3 = a0;
    for (int d = 0; d < Cc; d += 4) {
        float4 u0 = *(const float4*)(base + (size_t)(d + 0) * Nn);
        float4 u1 = *(const float4*)(base + (size_t)(d + 1) * Nn);
        float4 u2 = *(const float4*)(base + (size_t)(d + 2) * Nn);
        float4 u3 = *(const float4*)(base + (size_t)(d + 3) * Nn);
        a0.x += u0.x; a0.y += u0.y; a0.z += u0.z; a0.w += u0.w;
        a1.x += u1.x; a1.y += u1.y; a1.z += u1.z; a1.w += u1.w;
        a2.x += u2.x; a2.y += u2.y; a2.z += u2.z; a2.w += u2.w;
        a3.x += u3.x; a3.y += u3.y; a3.z += u3.z; a3.w += u3.w;
    }
    float4 s = make_float4(a0.x + a1.x + a2.x + a3.x, a0.y + a1.y + a2.y + a3.y,
                           a0.z + a1.z + a2.z + a3.z, a0.w + a1.w + a2.w + a3.w);
    *(float4*)&g_S[b][n0 + t * 4] = s;
}

// ---------------------------------------------------------------------------
// Kernel 1: Gram split-K partials via HMMA bf16 (hi/lo 3-pass), in-kernel split.
// Block = (sp, b), 8 warps. Tile M=128 x N=128, K-chunk = 64. Warp: 32m x 64n.
// ---------------------------------------------------------------------------
__global__ __launch_bounds__(256, 2)
void k_gram_mma(const float* __restrict__ x) {
    __shared__ __align__(16) __nv_bfloat16 sH[128][72];
    __shared__ __align__(16) __nv_bfloat16 sL[128][72];

    const int b  = blockIdx.y;
    const int sp = blockIdx.x;
    const int tid = threadIdx.x;
    const int wid = tid >> 5, lane = tid & 31;
    const int wm = wid & 3, wn = wid >> 2;

    const unsigned uH = smem_u32(&sH[0][0]);
    const unsigned uL = smem_u32(&sL[0][0]);

    float acc[2][8][4];
#pragma unroll
    for (int mi = 0; mi < 2; mi++)
#pragma unroll
        for (int nb = 0; nb < 8; nb++)
#pragma unroll
            for (int q = 0; q < 4; q++) acc[mi][nb][q] = 0.f;

    const int arow = wm * 32 + (lane & 15);
    const int acolq = (lane >> 4) * 8;
    const int brow = (lane & 7) + ((lane >> 4) & 1) * 8;
    const int bcolq = ((lane >> 3) & 1) * 8;

    const size_t kb0 = (size_t)sp * KCHUNK_G;
    const int NIT = KCHUNK_G / 64;   // 32

    for (int it = 0; it < NIT; it++) {
        const size_t kb = kb0 + (size_t)it * 64;
        __syncthreads();
#pragma unroll
        for (int q = 0; q < 4; q++) {
            const int idx = tid + q * 256;        // 0..1023
            const int row = idx >> 3, c8 = idx & 7;
            const float* src = x + (size_t)(b * Cc + row) * Nn + kb + c8 * 8;
            float4 v0 = *(const float4*)src;
            float4 v1 = *(const float4*)(src + 4);
            uint4 hq, lq;
            split8(v0, v1, hq, lq);
            *(uint4*)&sH[row][c8 * 8] = hq;
            *(uint4*)&sL[row][c8 * 8] = lq;
        }
        __syncthreads();

#pragma unroll
        for (int kk = 0; kk < 4; kk++) {
            unsigned aH[2][4], aL[2][4];
#pragma unroll
            for (int mi = 0; mi < 2; mi++) {
                const unsigned ao =
                    (unsigned)(((arow + mi * 16) * 72 + kk * 16 + acolq) * 2);
                ldsm4(aH[mi], uH + ao);
                ldsm4(aL[mi], uL + ao);
            }
#pragma unroll
            for (int ni = 0; ni < 4; ni++) {
                unsigned bH[4], bL[4];
                const unsigned bo =
                    (unsigned)(((wn * 64 + ni * 16 + brow) * 72 + kk * 16 + bcolq) * 2);
                ldsm4(bH, uH + bo);
                ldsm4(bL, uL + bo);
#pragma unroll
                for (int mi = 0; mi < 2; mi++) {
                    mma16816(acc[mi][2 * ni],     aH[mi], &bH[0]);
                    mma16816(acc[mi][2 * ni],     aH[mi], &bL[0]);
                    mma16816(acc[mi][2 * ni],     aL[mi], &bH[0]);
                    mma16816(acc[mi][2 * ni + 1], aH[mi], &bH[2]);
                    mma16816(acc[mi][2 * ni + 1], aH[mi], &bL[2]);
                    mma16816(acc[mi][2 * ni + 1], aL[mi], &bH[2]);
                }
            }
        }
    }

    float* gp = &g_part[sp][b][0][0];
#pragma unroll
    for (int mi = 0; mi < 2; mi++) {
        const int r0 = wm * 32 + mi * 16 + (lane >> 2);
#pragma unroll
        for (int nb = 0; nb < 8; nb++) {
            const int col = wn * 64 + nb * 8 + (lane & 3) * 2;
            *(float2*)(gp + (size_t)r0 * Cc + col) =
                make_float2(acc[mi][nb][0], acc[mi][nb][1]);
            *(float2*)(gp + (size_t)(r0 + 8) * Cc + col) =
                make_float2(acc[mi][nb][2], acc[mi][nb][3]);
        }
    }
}

// ---------------------------------------------------------------------------
// Kernel 2: reduce split-K partials -> G; row max; bf16 hi/lo of G.
// ---------------------------------------------------------------------------
__global__ __launch_bounds__(128)
void k_reduce() {
    const int c = blockIdx.x, b = blockIdx.y;
    const int d = threadIdx.x;
    float s = 0.f;
#pragma unroll
    for (int sp = 0; sp < SPLITG; sp++) s += g_part[sp][b][c][d];

    float m = s;
#pragma unroll
    for (int o = 16; o; o >>= 1) m = fmaxf(m, __shfl_xor_sync(0xffffffffu, m, o));
    __shared__ float wm[4];
    if ((d & 31) == 0) wm[d >> 5] = m;
    __syncthreads();
    m = fmaxf(fmaxf(wm[0], wm[1]), fmaxf(wm[2], wm[3]));

    __nv_bfloat16 h = __float2bfloat16_rn(s);
    g_Gh[b][c][d] = h;
    g_Gl[b][c][d] = __float2bfloat16_rn(s - __bfloat162float(h));
    if (d == 0) g_m[b][c] = m;
}

// ---------------------------------------------------------------------------
// Kernel 3: att2 = m_c * S[n] - (G*f)[c,n] via HMMA bf16 (hi/lo 3-pass).
// Block = (ntile, b), 8 warps. M=128(c) x N=128(n), K=128(d), chunk 32.
// B (f) read fp32, split in-kernel. Epilogue applies the exact rank-1 term.
// ---------------------------------------------------------------------------
__global__ __launch_bounds__(256, 2)
void k_gemm2_mma(const float* __restrict__ x) {
    __shared__ __align__(16) __nv_bfloat16 sAh[128][40];
    __shared__ __align__(16) __nv_bfloat16 sAl[128][40];
    __shared__ __align__(16) __nv_bfloat16 sBh[32][136];
    __shared__ __align__(16) __nv_bfloat16 sBl[32][136];

    const int b  = blockIdx.y;
    const int n0 = blockIdx.x * 128;
    const int tid = threadIdx.x;
    const int wid = tid >> 5, lane = tid & 31;
    const int wm = wid & 3, wn = wid >> 2;

    const unsigned uAh = smem_u32(&sAh[0][0]);
    const unsigned uAl = smem_u32(&sAl[0][0]);
    const unsigned uBh = smem_u32(&sBh[0][0]);
    const unsigned uBl = smem_u32(&sBl[0][0]);

    float acc[2][8][4];
#pragma unroll
    for (int mi = 0; mi < 2; mi++)
#pragma unroll
        for (int nb = 0; nb < 8; nb++)
#pragma unroll
            for (int q = 0; q < 4; q++) acc[mi][nb][q] = 0.f;

    const int arow = wm * 32 + (lane & 15);
    const int acolq = (lane >> 4) * 8;
    const int btrow = lane & 15;
    const int btcolq = (lane >> 4) * 8;

    for (int kt = 0; kt < 4; kt++) {
        const int k0 = kt * 32;
        __syncthreads();
        {   // stage A chunk: 128 c x 32 k bf16 hi/lo (pre-split in k_reduce)
#pragma unroll
            for (int q = 0; q < 2; q++) {
                const int idx = tid + q * 256;   // 0..511
                const int row = idx >> 2, c8 = idx & 3;
                *(uint4*)&sAh[row][c8 * 8] = *(const uint4*)&g_Gh[b][row][k0 + c8 * 8];
                *(uint4*)&sAl[row][c8 * 8] = *(const uint4*)&g_Gl[b][row][k0 + c8 * 8];
            }
            // stage B chunk: 32 k x 128 n, fp32 -> bf16 hi/lo split
#pragma unroll
            for (int q = 0; q < 2; q++) {
                const int idx = tid + q * 256;   // 0..511
                const int row = idx >> 4, c8 = idx & 15;
                const float* src = x + (size_t)(b * Cc + k0 + row) * Nn + n0 + c8 * 8;
                float4 v0 = *(const float4*)src;
                float4 v1 = *(const float4*)(src + 4);
                uint4 hq, lq;
                split8(v0, v1, hq, lq);
                *(uint4*)&sBh[row][c8 * 8] = hq;
                *(uint4*)&sBl[row][c8 * 8] = lq;
            }
        }
        __syncthreads();

#pragma unroll
        for (int kk = 0; kk < 2; kk++) {
            unsigned aH[2][4], aL[2][4];
#pragma unroll
            for (int mi = 0; mi < 2; mi++) {
                const unsigned ao =
                    (unsigned)(((arow + mi * 16) * 40 + kk * 16 + acolq) * 2);
                ldsm4(aH[mi], uAh + ao);
                ldsm4(aL[mi], uAl + ao);
            }
#pragma unroll
            for (int ni = 0; ni < 4; ni++) {
                unsigned bH[4], bL[4];
                const unsigned bo = (unsigned)(
                    ((kk * 16 + btrow) * 136 + wn * 64 + ni * 16 + btcolq) * 2);
                ldsm4t(bH, uBh + bo);
                ldsm4t(bL, uBl + bo);
#pragma unroll
                for (int mi = 0; mi < 2; mi++) {
                    mma16816(acc[mi][2 * ni],     aH[mi], &bH[0]);
                    mma16816(acc[mi][2 * ni],     aH[mi], &bL[0]);
                    mma16816(acc[mi][2 * ni],     aL[mi], &bH[0]);
                    mma16816(acc[mi][2 * ni + 1], aH[mi], &bH[2]);
                    mma16816(acc[mi][2 * ni + 1], aH[mi], &bL[2]);
                    mma16816(acc[mi][2 * ni + 1], aL[mi], &bH[2]);
                }
            }
        }
    }

    // epilogue: att2 = m_c * S[n] - acc
    float* op = g_att2 + (size_t)b * Cc * Nn;
#pragma unroll
    for (int mi = 0; mi < 2; mi++) {
        const int r0 = wm * 32 + mi * 16 + (lane >> 2);
        const float m0 = g_m[b][r0];
        const float m1 = g_m[b][r0 + 8];
#pragma unroll
        for (int nb = 0; nb < 8; nb++) {
            const int col = n0 + wn * 64 + nb * 8 + (lane & 3) * 2;
            const float2 Sv = *(const float2*)&g_S[b][col];
            *(float2*)(op + (size_t)r0 * Nn + col) =
                make_float2(m0 * Sv.x - acc[mi][nb][0],
                            m0 * Sv.y - acc[mi][nb][1]);
            *(float2*)(op + (size_t)(r0 + 8) * Nn + col) =
                make_float2(m1 * Sv.x - acc[mi][nb][2],
                            m1 * Sv.y - acc[mi][nb][3]);
        }
    }
}

// ---------------------------------------------------------------------------
// Kernel 4: depthwise 3x3 conv + bias + softmax(W) + outputs.
// Block = (c, b, half): 64 output rows, 66-row halo in smem.
// ---------------------------------------------------------------------------
__global__ __launch_bounds__(256)
void k_conv(const float* __restrict__ x, const float* __restrict__ dwW,
            const float* __restrict__ dwB, const float* __restrict__ gamma,
            float* __restrict__ out) {
    __shared__ float sm[66 * 132];
    const int c = blockIdx.x, b = blockIdx.y;
    const int r0 = blockIdx.z * 64;
    const int tid = threadIdx.x;

    for (int i = tid; i < 66 * 132; i += 256) sm[i] = 0.f;
    __syncthreads();

    const float* __restrict__ pl = g_att2 + ((size_t)b * Cc + c) * Nn;
    for (int idx4 = tid; idx4 < 66 * 32; idx4 += 256) {
        const int i = idx4 >> 5, w4 = (idx4 & 31) << 2;
        const int gr = r0 - 1 + i;
        if (gr >= 0 && gr < Hh) {
            float4 u = *(const float4*)(pl + gr * Ww + w4);
            float* rp = sm + i * 132 + 1 + w4;
            rp[0] = u.x; rp[1] = u.y; rp[2] = u.z; rp[3] = u.w;
        }
    }

    float w9[9];
#pragma unroll
    for (int i = 0; i < 9; i++) w9[i] = dwW[c * 9 + i];
    const float bz = dwB[c];
    const float gm = gamma[0];
    __syncthreads();

    const int warp = tid >> 5, lane = tid & 31;
    const float* __restrict__ xp = x + ((size_t)b * Cc + c) * Nn;
    float* __restrict__ op = out + ((size_t)b * Cc + c) * Nn;
    float* __restrict__ ap = out + (size_t)Bb * Cc * Nn + ((size_t)b * Cc + c) * Nn;

    for (int hh = warp; hh < 64; hh += 8) {
        const int h = r0 + hh;
        const int li = hh + 1;
        const int wb = lane << 2;
        float r0v[8], r1v[8], r2v[8];
        {
            float4 a0 = *(const float4*)&sm[(li - 1) * 132 + wb];
            float4 a1 = *(const float4*)&sm[(li - 1) * 132 + wb + 4];
            r0v[0]=a0.x; r0v[1]=a0.y; r0v[2]=a0.z; r0v[3]=a0.w;
            r0v[4]=a1.x; r0v[5]=a1.y; r0v[6]=a1.z; r0v[7]=a1.w;
            float4 b0 = *(const float4*)&sm[(li + 0) * 132 + wb];
            float4 b1 = *(const float4*)&sm[(li + 0) * 132 + wb + 4];
            r1v[0]=b0.x; r1v[1]=b0.y; r1v[2]=b0.z; r1v[3]=b0.w;
            r1v[4]=b1.x; r1v[5]=b1.y; r1v[6]=b1.z; r1v[7]=b1.w;
            float4 c0 = *(const float4*)&sm[(li + 1) * 132 + wb];
            float4 c1 = *(const float4*)&sm[(li + 1) * 132 + wb + 4];
            r2v[0]=c0.x; r2v[1]=c0.y; r2v[2]=c0.z; r2v[3]=c0.w;
            r2v[4]=c1.x; r2v[5]=c1.y; r2v[6]=c1.z; r2v[7]=c1.w;
        }
        float v[4];
#pragma unroll
        for (int j = 0; j < 4; j++) {
            float s = bz;
            s = fmaf(r0v[j],     w9[0], s);
            s = fmaf(r0v[j + 1], w9[1], s);
            s = fmaf(r0v[j + 2], w9[2], s);
            s = fmaf(r1v[j],     w9[3], s);
            s = fmaf(r1v[j + 1], w9[4], s);
            s = fmaf(r1v[j + 2], w9[5], s);
            s = fmaf(r2v[j],     w9[6], s);
            s = fmaf(r2v[j + 1], w9[7], s);
            s = fmaf(r2v[j + 2], w9[8], s);
            v[j] = s;
        }
        float mx = fmaxf(fmaxf(v[0], v[1]), fmaxf(v[2], v[3]));
#pragma unroll
        for (int o = 16; o; o >>= 1) mx = fmaxf(mx, __shfl_xor_sync(0xffffffffu, mx, o));
        float e[4]; float ssum = 0.f;
#pragma unroll
        for (int j = 0; j < 4; j++) { e[j] = __expf(v[j] - mx); ssum += e[j]; }
#pragma unroll
        for (int o = 16; o; o >>= 1) ssum += __shfl_xor_sync(0xffffffffu, ssum, o);
        const float inv = 1.0f / ssum;

        float4 xv = *(const float4*)(xp + h * Ww + wb);
        float4 av = make_float4(e[0] * inv, e[1] * inv, e[2] * inv, e[3] * inv);
        *(float4*)(ap + h * Ww + wb) = av;
        *(float4*)(op + h * Ww + wb) = make_float4(
            fmaf(gm, av.x, xv.x), fmaf(gm, av.y, xv.y),
            fmaf(gm, av.z, xv.z), fmaf(gm, av.w, xv.w));
    }
}

// ---------------------------------------------------------------------------
extern "C" void kernel_launch(void* const* d_in, const int* in_sizes, int n_in,
                              void* d_out, int out_size) {
    (void)in_sizes; (void)n_in; (void)out_size;
    const float* x    = (const float*)d_in[0];
    const float* dwW  = (const float*)d_in[1];
    const float* dwB  = (const float*)d_in[2];
    const float* gm   = (const float*)d_in[3];
    float* out = (float*)d_out;

    k_sums     <<<dim3(Nn / 512, Bb), 128>>>(x);
    k_gram_mma <<<dim3(SPLITG, Bb), 256>>>(x);
    k_reduce   <<<dim3(Cc, Bb), 128>>>();
    k_gemm2_mma<<<dim3(Nn / 128, Bb), 256>>>(x);
    k_conv     <<<dim3(Cc, Bb, 2), 256>>>(x, dwW, dwB, gm, out);
}

// round 7
// speedup vs baseline: 1.6325x; 1.0345x over previous
#include <cuda_runtime.h>
#include <cuda_bf16.h>

#define Bb 16
#define Cc 128
#define Hh 128
#define Ww 128
#define Nn 16384          // Hh*Ww
#define SPLITG 16         // split-K for Gram (grid = 256 = full single wave)
#define KCHUNK_G 1024     // Nn / SPLITG

// ---------------- scratch (static device globals) ----------------
static __device__ float g_part[SPLITG][Bb][Cc][Cc];         // 16 MB Gram split-K partials
static __device__ __nv_bfloat16 g_Gh[Bb][Cc][Cc];           // G hi
static __device__ __nv_bfloat16 g_Gl[Bb][Cc][Cc];           // G lo
static __device__ float g_m[Bb][Cc];                        // row max of G
static __device__ float g_S[Bb][Nn];                        // column sums of f (fp32 exact)
static __device__ float g_att2[(size_t)Bb * Cc * Nn];       // 134 MB pre-conv tensor

// ---------------- mma / ldmatrix helpers (plain PTX, sm_80+) ----------------
__device__ __forceinline__ unsigned smem_u32(const void* p) {
    unsigned a;
    asm("{ .reg .u64 t; cvta.to.shared.u64 t, %1; cvt.u32.u64 %0, t; }"
        : "=r"(a) : "l"(p));
    return a;
}
__device__ __forceinline__ void ldsm4(unsigned* r, unsigned addr) {
    asm volatile("ldmatrix.sync.aligned.m8n8.x4.shared.b16 {%0,%1,%2,%3}, [%4];"
                 : "=r"(r[0]), "=r"(r[1]), "=r"(r[2]), "=r"(r[3]) : "r"(addr));
}
__device__ __forceinline__ void ldsm4t(unsigned* r, unsigned addr) {
    asm volatile("ldmatrix.sync.aligned.m8n8.x4.trans.shared.b16 {%0,%1,%2,%3}, [%4];"
                 : "=r"(r[0]), "=r"(r[1]), "=r"(r[2]), "=r"(r[3]) : "r"(addr));
}
__device__ __forceinline__ void mma16816(float* c, const unsigned* a, const unsigned* b) {
    asm volatile(
        "mma.sync.aligned.m16n8k16.row.col.f32.bf16.bf16.f32 "
        "{%0,%1,%2,%3}, {%4,%5,%6,%7}, {%8,%9}, {%0,%1,%2,%3};"
        : "+f"(c[0]), "+f"(c[1]), "+f"(c[2]), "+f"(c[3])
        : "r"(a[0]), "r"(a[1]), "r"(a[2]), "r"(a[3]), "r"(b[0]), "r"(b[1]));
}

// split 8 fp32 -> 8 bf16 hi + 8 bf16 lo (packed as uint4 each)
__device__ __forceinline__ void split8(const float4 v0, const float4 v1,
                                       uint4& h, uint4& l) {
    __nv_bfloat162 h0 = __floats2bfloat162_rn(v0.x, v0.y);
    __nv_bfloat162 h1 = __floats2bfloat162_rn(v0.z, v0.w);
    __nv_bfloat162 h2 = __floats2bfloat162_rn(v1.x, v1.y);
    __nv_bfloat162 h3 = __floats2bfloat162_rn(v1.z, v1.w);
    unsigned b0 = *(unsigned*)&h0, b1 = *(unsigned*)&h1;
    unsigned b2 = *(unsigned*)&h2, b3 = *(unsigned*)&h3;
    float f0x = __uint_as_float(b0 << 16), f0y = __uint_as_float(b0 & 0xffff0000u);
    float f1x = __uint_as_float(b1 << 16), f1y = __uint_as_float(b1 & 0xffff0000u);
    float f2x = __uint_as_float(b2 << 16), f2y = __uint_as_float(b2 & 0xffff0000u);
    float f3x = __uint_as_float(b3 << 16), f3y = __uint_as_float(b3 & 0xffff0000u);
    __nv_bfloat162 l0 = __floats2bfloat162_rn(v0.x - f0x, v0.y - f0y);
    __nv_bfloat162 l1 = __floats2bfloat162_rn(v0.z - f1x, v0.w - f1y);
    __nv_bfloat162 l2 = __floats2bfloat162_rn(v1.x - f2x, v1.y - f2y);
    __nv_bfloat162 l3 = __floats2bfloat162_rn(v1.z - f3x, v1.w - f3y);
    h = make_uint4(b0, b1, b2, b3);
    l = make_uint4(*(unsigned*)&l0, *(unsigned*)&l1,
                   *(unsigned*)&l2, *(unsigned*)&l3);
}

// ---------------------------------------------------------------------------
// Kernel S: exact fp32 column sums S[b][n] = sum_c x[b][c][n]
// ---------------------------------------------------------------------------
__global__ __launch_bounds__(128)
void k_sums(const float* __restrict__ x) {
    const int b = blockIdx.y;
    const int n0 = blockIdx.x * 512;
    const int t = threadIdx.x;
    const float* base = x + (size_t)b * Cc * Nn + n0 + t * 4;
    float4 a0 = make_float4(0.f, 0.f, 0.f, 0.f), a1 = a0, a2 = a0, a3 = a0;
    for (int d = 0; d < Cc; d += 4) {
        float4 u0 = *(const float4*)(base + (size_t)(d + 0) * Nn);
        float4 u1 = *(const float4*)(base + (size_t)(d + 1) * Nn);
        float4 u2 = *(const float4*)(base + (size_t)(d + 2) * Nn);
        float4 u3 = *(const float4*)(base + (size_t)(d + 3) * Nn);
        a0.x += u0.x; a0.y += u0.y; a0.z += u0.z; a0.w += u0.w;
        a1.x += u1.x; a1.y += u1.y; a1.z += u1.z; a1.w += u1.w;
        a2.x += u2.x; a2.y += u2.y; a2.z += u2.z; a2.w += u2.w;
        a3.x += u3.x; a3.y += u3.y; a3.z += u3.z; a3.w += u3.w;
    }
    float4 s = make_float4(a0.x + a1.x + a2.x + a3.x, a0.y + a1.y + a2.y + a3.y,
                           a0.z + a1.z + a2.z + a3.z, a0.w + a1.w + a2.w + a3.w);
    *(float4*)&g_S[b][n0 + t * 4] = s;
}

// ---------------------------------------------------------------------------
// Kernel 1: Gram split-K via HMMA bf16 (hi/lo 3-pass), register-prefetch pipe.
// Block = (sp, b), 8 warps. Tile M=128 x N=128, K-chunk = 64. Warp: 32m x 64n.
// ---------------------------------------------------------------------------
__global__ __launch_bounds__(256, 2)
void k_gram_mma(const float* __restrict__ x) {
    __shared__ __align__(16) __nv_bfloat16 sH[128][72];
    __shared__ __align__(16) __nv_bfloat16 sL[128][72];

    const int b  = blockIdx.y;
    const int sp = blockIdx.x;
    const int tid = threadIdx.x;
    const int wid = tid >> 5, lane = tid & 31;
    const int wm = wid & 3, wn = wid >> 2;

    const unsigned uH = smem_u32(&sH[0][0]);
    const unsigned uL = smem_u32(&sL[0][0]);

    float acc[2][8][4];
#pragma unroll
    for (int mi = 0; mi < 2; mi++)
#pragma unroll
        for (int nb = 0; nb < 8; nb++)
#pragma unroll
            for (int q = 0; q < 4; q++) acc[mi][nb][q] = 0.f;

    const int arow = wm * 32 + (lane & 15);
    const int acolq = (lane >> 4) * 8;
    const int brow = (lane & 7) + ((lane >> 4) & 1) * 8;
    const int bcolq = ((lane >> 3) & 1) * 8;

    const size_t kb0 = (size_t)sp * KCHUNK_G;
    const int NIT = KCHUNK_G / 64;   // 16

    const int prow = tid >> 3, pc8 = tid & 7;  // staging coords
    float4 pv[8];                              // prefetch registers

    // prologue: chunk 0
#pragma unroll
    for (int q = 0; q < 4; q++) {
        const float* src = x + (size_t)(b * Cc + prow + q * 32) * Nn + kb0 + pc8 * 8;
        pv[2 * q]     = *(const float4*)src;
        pv[2 * q + 1] = *(const float4*)(src + 4);
    }

    for (int it = 0; it < NIT; it++) {
        // convert + store prefetched chunk
#pragma unroll
        for (int q = 0; q < 4; q++) {
            uint4 hq, lq;
            split8(pv[2 * q], pv[2 * q + 1], hq, lq);
            *(uint4*)&sH[prow + q * 32][pc8 * 8] = hq;
            *(uint4*)&sL[prow + q * 32][pc8 * 8] = lq;
        }
        __syncthreads();
        // issue next chunk's LDGs (hidden under the MMA loop below)
        if (it + 1 < NIT) {
            const size_t kb = kb0 + (size_t)(it + 1) * 64;
#pragma unroll
            for (int q = 0; q < 4; q++) {
                const float* src = x + (size_t)(b * Cc + prow + q * 32) * Nn + kb + pc8 * 8;
                pv[2 * q]     = *(const float4*)src;
                pv[2 * q + 1] = *(const float4*)(src + 4);
            }
        }

#pragma unroll
        for (int kk = 0; kk < 4; kk++) {
            unsigned aH[2][4], aL[2][4];
#pragma unroll
            for (int mi = 0; mi < 2; mi++) {
                const unsigned ao =
                    (unsigned)(((arow + mi * 16) * 72 + kk * 16 + acolq) * 2);
                ldsm4(aH[mi], uH + ao);
                ldsm4(aL[mi], uL + ao);
            }
#pragma unroll
            for (int ni = 0; ni < 4; ni++) {
                unsigned bH[4], bL[4];
                const unsigned bo =
                    (unsigned)(((wn * 64 + ni * 16 + brow) * 72 + kk * 16 + bcolq) * 2);
                ldsm4(bH, uH + bo);
                ldsm4(bL, uL + bo);
#pragma unroll
                for (int mi = 0; mi < 2; mi++) {
                    mma16816(acc[mi][2 * ni],     aH[mi], &bH[0]);
                    mma16816(acc[mi][2 * ni],     aH[mi], &bL[0]);
                    mma16816(acc[mi][2 * ni],     aL[mi], &bH[0]);
                    mma16816(acc[mi][2 * ni + 1], aH[mi], &bH[2]);
                    mma16816(acc[mi][2 * ni + 1], aH[mi], &bL[2]);
                    mma16816(acc[mi][2 * ni + 1], aL[mi], &bH[2]);
                }
            }
        }
        __syncthreads();
    }

    float* gp = &g_part[sp][b][0][0];
#pragma unroll
    for (int mi = 0; mi < 2; mi++) {
        const int r0 = wm * 32 + mi * 16 + (lane >> 2);
#pragma unroll
        for (int nb = 0; nb < 8; nb++) {
            const int col = wn * 64 + nb * 8 + (lane & 3) * 2;
            *(float2*)(gp + (size_t)r0 * Cc + col) =
                make_float2(acc[mi][nb][0], acc[mi][nb][1]);
            *(float2*)(gp + (size_t)(r0 + 8) * Cc + col) =
                make_float2(acc[mi][nb][2], acc[mi][nb][3]);
        }
    }
}

// ---------------------------------------------------------------------------
// Kernel 2: reduce split-K partials -> G; row max; bf16 hi/lo of G.
// ---------------------------------------------------------------------------
__global__ __launch_bounds__(128)
void k_reduce() {
    const int c = blockIdx.x, b = blockIdx.y;
    const int d = threadIdx.x;
    float s = 0.f;
#pragma unroll
    for (int sp = 0; sp < SPLITG; sp++) s += g_part[sp][b][c][d];

    float m = s;
#pragma unroll
    for (int o = 16; o; o >>= 1) m = fmaxf(m, __shfl_xor_sync(0xffffffffu, m, o));
    __shared__ float wm[4];
    if ((d & 31) == 0) wm[d >> 5] = m;
    __syncthreads();
    m = fmaxf(fmaxf(wm[0], wm[1]), fmaxf(wm[2], wm[3]));

    __nv_bfloat16 h = __float2bfloat16_rn(s);
    g_Gh[b][c][d] = h;
    g_Gl[b][c][d] = __float2bfloat16_rn(s - __bfloat162float(h));
    if (d == 0) g_m[b][c] = m;
}

// ---------------------------------------------------------------------------
// Kernel 3: att2 = m_c * S[n] - (G*f)[c,n] via HMMA (hi/lo 3-pass), B-prefetch.
// Block = (ntile, b), 8 warps. M=128(c) x N=128(n), K=128(d), chunk 32.
// ---------------------------------------------------------------------------
__global__ __launch_bounds__(256, 2)
void k_gemm2_mma(const float* __restrict__ x) {
    __shared__ __align__(16) __nv_bfloat16 sAh[128][40];
    __shared__ __align__(16) __nv_bfloat16 sAl[128][40];
    __shared__ __align__(16) __nv_bfloat16 sBh[32][136];
    __shared__ __align__(16) __nv_bfloat16 sBl[32][136];

    const int b  = blockIdx.y;
    const int n0 = blockIdx.x * 128;
    const int tid = threadIdx.x;
    const int wid = tid >> 5, lane = tid & 31;
    const int wm = wid & 3, wn = wid >> 2;

    const unsigned uAh = smem_u32(&sAh[0][0]);
    const unsigned uAl = smem_u32(&sAl[0][0]);
    const unsigned uBh = smem_u32(&sBh[0][0]);
    const unsigned uBl = smem_u32(&sBl[0][0]);

    float acc[2][8][4];
#pragma unroll
    for (int mi = 0; mi < 2; mi++)
#pragma unroll
        for (int nb = 0; nb < 8; nb++)
#pragma unroll
            for (int q = 0; q < 4; q++) acc[mi][nb][q] = 0.f;

    const int arow = wm * 32 + (lane & 15);
    const int acolq = (lane >> 4) * 8;
    const int btrow = lane & 15;
    const int btcolq = (lane >> 4) * 8;

    const int prow = tid >> 4, pc8 = tid & 15;  // B staging coords
    float4 pB[4];

    // prologue: B chunk 0
#pragma unroll
    for (int q = 0; q < 2; q++) {
        const float* src = x + (size_t)(b * Cc + prow + q * 16) * Nn + n0 + pc8 * 8;
        pB[2 * q]     = *(const float4*)src;
        pB[2 * q + 1] = *(const float4*)(src + 4);
    }

    for (int kt = 0; kt < 4; kt++) {
        const int k0 = kt * 32;
        // stage A chunk just-in-time (L2-hot G) + store prefetched B
#pragma unroll
        for (int q = 0; q < 2; q++) {
            const int idx = tid + q * 256;
            const int row = idx >> 2, c8 = idx & 3;
            *(uint4*)&sAh[row][c8 * 8] = *(const uint4*)&g_Gh[b][row][k0 + c8 * 8];
            *(uint4*)&sAl[row][c8 * 8] = *(const uint4*)&g_Gl[b][row][k0 + c8 * 8];
        }
#pragma unroll
        for (int q = 0; q < 2; q++) {
            uint4 hq, lq;
            split8(pB[2 * q], pB[2 * q + 1], hq, lq);
            *(uint4*)&sBh[prow + q * 16][pc8 * 8] = hq;
            *(uint4*)&sBl[prow + q * 16][pc8 * 8] = lq;
        }
        __syncthreads();
        // issue next B chunk's LDGs
        if (kt + 1 < 4) {
            const int k1 = (kt + 1) * 32;
#pragma unroll
            for (int q = 0; q < 2; q++) {
                const float* src =
                    x + (size_t)(b * Cc + k1 + prow + q * 16) * Nn + n0 + pc8 * 8;
                pB[2 * q]     = *(const float4*)src;
                pB[2 * q + 1] = *(const float4*)(src + 4);
            }
        }

#pragma unroll
        for (int kk = 0; kk < 2; kk++) {
            unsigned aH[2][4], aL[2][4];
#pragma unroll
            for (int mi = 0; mi < 2; mi++) {
                const unsigned ao =
                    (unsigned)(((arow + mi * 16) * 40 + kk * 16 + acolq) * 2);
                ldsm4(aH[mi], uAh + ao);
                ldsm4(aL[mi], uAl + ao);
            }
#pragma unroll
            for (int ni = 0; ni < 4; ni++) {
                unsigned bH[4], bL[4];
                const unsigned bo = (unsigned)(
                    ((kk * 16 + btrow) * 136 + wn * 64 + ni * 16 + btcolq) * 2);
                ldsm4t(bH, uBh + bo);
                ldsm4t(bL, uBl + bo);
#pragma unroll
                for (int mi = 0; mi < 2; mi++) {
                    mma16816(acc[mi][2 * ni],     aH[mi], &bH[0]);
                    mma16816(acc[mi][2 * ni],     aH[mi], &bL[0]);
                    mma16816(acc[mi][2 * ni],     aL[mi], &bH[0]);
                    mma16816(acc[mi][2 * ni + 1], aH[mi], &bH[2]);
                    mma16816(acc[mi][2 * ni + 1], aH[mi], &bL[2]);
                    mma16816(acc[mi][2 * ni + 1], aL[mi], &bH[2]);
                }
            }
        }
        __syncthreads();
    }

    // epilogue: att2 = m_c * S[n] - acc
    float* op = g_att2 + (size_t)b * Cc * Nn;
#pragma unroll
    for (int mi = 0; mi < 2; mi++) {
        const int r0 = wm * 32 + mi * 16 + (lane >> 2);
        const float m0 = g_m[b][r0];
        const float m1 = g_m[b][r0 + 8];
#pragma unroll
        for (int nb = 0; nb < 8; nb++) {
            const int col = n0 + wn * 64 + nb * 8 + (lane & 3) * 2;
            const float2 Sv = *(const float2*)&g_S[b][col];
            *(float2*)(op + (size_t)r0 * Nn + col) =
                make_float2(m0 * Sv.x - acc[mi][nb][0],
                            m0 * Sv.y - acc[mi][nb][1]);
            *(float2*)(op + (size_t)(r0 + 8) * Nn + col) =
                make_float2(m1 * Sv.x - acc[mi][nb][2],
                            m1 * Sv.y - acc[mi][nb][3]);
        }
    }
}

// ---------------------------------------------------------------------------
// Kernel 4: depthwise 3x3 conv + bias + softmax(W) + outputs.
// Block = (c, b, half): 64 output rows, 66-row halo in smem.
// ---------------------------------------------------------------------------
__global__ __launch_bounds__(256)
void k_conv(const float* __restrict__ x, const float* __restrict__ dwW,
            const float* __restrict__ dwB, const float* __restrict__ gamma,
            float* __restrict__ out) {
    __shared__ float sm[66 * 132];
    const int c = blockIdx.x, b = blockIdx.y;
    const int r0 = blockIdx.z * 64;
    const int tid = threadIdx.x;

    for (int i = tid; i < 66 * 132; i += 256) sm[i] = 0.f;
    __syncthreads();

    const float* __restrict__ pl = g_att2 + ((size_t)b * Cc + c) * Nn;
    for (int idx4 = tid; idx4 < 66 * 32; idx4 += 256) {
        const int i = idx4 >> 5, w4 = (idx4 & 31) << 2;
        const int gr = r0 - 1 + i;
        if (gr >= 0 && gr < Hh) {
            float4 u = *(const float4*)(pl + gr * Ww + w4);
            float* rp = sm + i * 132 + 1 + w4;
            rp[0] = u.x; rp[1] = u.y; rp[2] = u.z; rp[3] = u.w;
        }
    }

    float w9[9];
#pragma unroll
    for (int i = 0; i < 9; i++) w9[i] = dwW[c * 9 + i];
    const float bz = dwB[c];
    const float gm = gamma[0];
    __syncthreads();

    const int warp = tid >> 5, lane = tid & 31;
    const float* __restrict__ xp = x + ((size_t)b * Cc + c) * Nn;
    float* __restrict__ op = out + ((size_t)b * Cc + c) * Nn;
    float* __restrict__ ap = out + (size_t)Bb * Cc * Nn + ((size_t)b * Cc + c) * Nn;

    for (int hh = warp; hh < 64; hh += 8) {
        const int h = r0 + hh;
        const int li = hh + 1;
        const int wb = lane << 2;
        float r0v[8], r1v[8], r2v[8];
        {
            float4 a0 = *(const float4*)&sm[(li - 1) * 132 + wb];
            float4 a1 = *(const float4*)&sm[(li - 1) * 132 + wb + 4];
            r0v[0]=a0.x; r0v[1]=a0.y; r0v[2]=a0.z; r0v[3]=a0.w;
            r0v[4]=a1.x; r0v[5]=a1.y; r0v[6]=a1.z; r0v[7]=a1.w;
            float4 b0 = *(const float4*)&sm[(li + 0) * 132 + wb];
            float4 b1 = *(const float4*)&sm[(li + 0) * 132 + wb + 4];
            r1v[0]=b0.x; r1v[1]=b0.y; r1v[2]=b0.z; r1v[3]=b0.w;
            r1v[4]=b1.x; r1v[5]=b1.y; r1v[6]=b1.z; r1v[7]=b1.w;
            float4 c0 = *(const float4*)&sm[(li + 1) * 132 + wb];
            float4 c1 = *(const float4*)&sm[(li + 1) * 132 + wb + 4];
            r2v[0]=c0.x; r2v[1]=c0.y; r2v[2]=c0.z; r2v[3]=c0.w;
            r2v[4]=c1.x; r2v[5]=c1.y; r2v[6]=c1.z; r2v[7]=c1.w;
        }
        float v[4];
#pragma unroll
        for (int j = 0; j < 4; j++) {
            float s = bz;
            s = fmaf(r0v[j],     w9[0], s);
            s = fmaf(r0v[j + 1], w9[1], s);
            s = fmaf(r0v[j + 2], w9[2], s);
            s = fmaf(r1v[j],     w9[3], s);
            s = fmaf(r1v[j + 1], w9[4], s);
            s = fmaf(r1v[j + 2], w9[5], s);
            s = fmaf(r2v[j],     w9[6], s);
            s = fmaf(r2v[j + 1], w9[7], s);
            s = fmaf(r2v[j + 2], w9[8], s);
            v[j] = s;
        }
        float mx = fmaxf(fmaxf(v[0], v[1]), fmaxf(v[2], v[3]));
#pragma unroll
        for (int o = 16; o; o >>= 1) mx = fmaxf(mx, __shfl_xor_sync(0xffffffffu, mx, o));
        float e[4]; float ssum = 0.f;
#pragma unroll
        for (int j = 0; j < 4; j++) { e[j] = __expf(v[j] - mx); ssum += e[j]; }
#pragma unroll
        for (int o = 16; o; o >>= 1) ssum += __shfl_xor_sync(0xffffffffu, ssum, o);
        const float inv = 1.0f / ssum;

        float4 xv = *(const float4*)(xp + h * Ww + wb);
        float4 av = make_float4(e[0] * inv, e[1] * inv, e[2] * inv, e[3] * inv);
        *(float4*)(ap + h * Ww + wb) = av;
        *(float4*)(op + h * Ww + wb) = make_float4(
            fmaf(gm, av.x, xv.x), fmaf(gm, av.y, xv.y),
            fmaf(gm, av.z, xv.z), fmaf(gm, av.w, xv.w));
    }
}

// ---------------------------------------------------------------------------
extern "C" void kernel_launch(void* const* d_in, const int* in_sizes, int n_in,
                              void* d_out, int out_size) {
    (void)in_sizes; (void)n_in; (void)out_size;
    const float* x    = (const float*)d_in[0];
    const float* dwW  = (const float*)d_in[1];
    const float* dwB  = (const float*)d_in[2];
    const float* gm   = (const float*)d_in[3];
    float* out = (float*)d_out;

    k_sums     <<<dim3(Nn / 512, Bb), 128>>>(x);
    k_gram_mma <<<dim3(SPLITG, Bb), 256>>>(x);
    k_reduce   <<<dim3(Cc, Bb), 128>>>();
    k_gemm2_mma<<<dim3(Nn / 128, Bb), 256>>>(x);
    k_conv     <<<dim3(Cc, Bb, 2), 256>>>(x, dwW, dwB, gm, out);
}

// round 8
// speedup vs baseline: 1.8366x; 1.1251x over previous
#include <cuda_runtime.h>
#include <cuda_bf16.h>

#define Bb 16
#define Cc 128
#define Hh 128
#define Ww 128
#define Nn 16384          // Hh*Ww
#define SPLITG 16         // split-K for Gram
#define KCHUNK_G 1024     // Nn / SPLITG

// ---------------- scratch (static device globals) ----------------
static __device__ float g_part[SPLITG][Bb][Cc][Cc];         // 16 MB Gram split-K partials
static __device__ __nv_bfloat16 g_Gh[Bb][Cc][Cc];           // G hi
static __device__ __nv_bfloat16 g_Gl[Bb][Cc][Cc];           // G lo
static __device__ float g_m[Bb][Cc];                        // row max of G
static __device__ float g_S[Bb][Nn];                        // column sums of f (fp32 exact)
static __device__ float g_att2[(size_t)Bb * Cc * Nn];       // 134 MB pre-conv tensor

// ---------------- mma / ldmatrix helpers (plain PTX, sm_80+) ----------------
__device__ __forceinline__ unsigned smem_u32(const void* p) {
    unsigned a;
    asm("{ .reg .u64 t; cvta.to.shared.u64 t, %1; cvt.u32.u64 %0, t; }"
        : "=r"(a) : "l"(p));
    return a;
}
__device__ __forceinline__ void ldsm4(unsigned* r, unsigned addr) {
    asm volatile("ldmatrix.sync.aligned.m8n8.x4.shared.b16 {%0,%1,%2,%3}, [%4];"
                 : "=r"(r[0]), "=r"(r[1]), "=r"(r[2]), "=r"(r[3]) : "r"(addr));
}
__device__ __forceinline__ void ldsm4t(unsigned* r, unsigned addr) {
    asm volatile("ldmatrix.sync.aligned.m8n8.x4.trans.shared.b16 {%0,%1,%2,%3}, [%4];"
                 : "=r"(r[0]), "=r"(r[1]), "=r"(r[2]), "=r"(r[3]) : "r"(addr));
}
__device__ __forceinline__ void mma16816(float* c, const unsigned* a, const unsigned* b) {
    asm volatile(
        "mma.sync.aligned.m16n8k16.row.col.f32.bf16.bf16.f32 "
        "{%0,%1,%2,%3}, {%4,%5,%6,%7}, {%8,%9}, {%0,%1,%2,%3};"
        : "+f"(c[0]), "+f"(c[1]), "+f"(c[2]), "+f"(c[3])
        : "r"(a[0]), "r"(a[1]), "r"(a[2]), "r"(a[3]), "r"(b[0]), "r"(b[1]));
}

// split 8 fp32 -> 8 bf16 hi + 8 bf16 lo (packed as uint4 each)
__device__ __forceinline__ void split8(const float4 v0, const float4 v1,
                                       uint4& h, uint4& l) {
    __nv_bfloat162 h0 = __floats2bfloat162_rn(v0.x, v0.y);
    __nv_bfloat162 h1 = __floats2bfloat162_rn(v0.z, v0.w);
    __nv_bfloat162 h2 = __floats2bfloat162_rn(v1.x, v1.y);
    __nv_bfloat162 h3 = __floats2bfloat162_rn(v1.z, v1.w);
    unsigned b0 = *(unsigned*)&h0, b1 = *(unsigned*)&h1;
    unsigned b2 = *(unsigned*)&h2, b3 = *(unsigned*)&h3;
    float f0x = __uint_as_float(b0 << 16), f0y = __uint_as_float(b0 & 0xffff0000u);
    float f1x = __uint_as_float(b1 << 16), f1y = __uint_as_float(b1 & 0xffff0000u);
    float f2x = __uint_as_float(b2 << 16), f2y = __uint_as_float(b2 & 0xffff0000u);
    float f3x = __uint_as_float(b3 << 16), f3y = __uint_as_float(b3 & 0xffff0000u);
    __nv_bfloat162 l0 = __floats2bfloat162_rn(v0.x - f0x, v0.y - f0y);
    __nv_bfloat162 l1 = __floats2bfloat162_rn(v0.z - f1x, v0.w - f1y);
    __nv_bfloat162 l2 = __floats2bfloat162_rn(v1.x - f2x, v1.y - f2y);
    __nv_bfloat162 l3 = __floats2bfloat162_rn(v1.z - f3x, v1.w - f3y);
    h = make_uint4(b0, b1, b2, b3);
    l = make_uint4(*(unsigned*)&l0, *(unsigned*)&l1,
                   *(unsigned*)&l2, *(unsigned*)&l3);
}

// swizzled byte offset, 128B rows (gram tiles): row 0..127, col16 0..7
__device__ __forceinline__ unsigned sw128(int row, int col16) {
    return (unsigned)(row * 128 + ((col16 ^ (row & 7)) << 4));
}
// swizzled byte offset, 256B rows (gemm2 resident A): row 0..127, col16 0..15
__device__ __forceinline__ unsigned sw256(int row, int col16) {
    return (unsigned)(row * 256 + ((((col16 ^ row) & 7) | (col16 & 8)) << 4));
}

// ---------------------------------------------------------------------------
// Kernel 1: merged Gram (odd/even block split) + exact column sums.
// grid (32, Bb): even x -> gram split sp = x>>1; odd x -> sums chunk = x>>1.
// Gram: double-buffered swizzled smem, ONE sync per 64-K chunk.
// ---------------------------------------------------------------------------
__global__ __launch_bounds__(256, 2)
void k_gram_sums(const float* __restrict__ x) {
    extern __shared__ __align__(16) char dsm[];   // 65536 B: buf(2) x {H,L} x 128x64 halves
    const int b  = blockIdx.y;
    const int xb = blockIdx.x;
    const int tid = threadIdx.x;

    if (xb & 1) {
        // ---- sums role: 1024-column chunk ----
        const int n0 = (xb >> 1) * 1024;
        const float* base = x + (size_t)b * Cc * Nn + n0 + tid * 4;
        float4 a0 = make_float4(0.f, 0.f, 0.f, 0.f), a1 = a0, a2 = a0, a3 = a0;
        for (int d = 0; d < Cc; d += 4) {
            float4 u0 = *(const float4*)(base + (size_t)(d + 0) * Nn);
            float4 u1 = *(const float4*)(base + (size_t)(d + 1) * Nn);
            float4 u2 = *(const float4*)(base + (size_t)(d + 2) * Nn);
            float4 u3 = *(const float4*)(base + (size_t)(d + 3) * Nn);
            a0.x += u0.x; a0.y += u0.y; a0.z += u0.z; a0.w += u0.w;
            a1.x += u1.x; a1.y += u1.y; a1.z += u1.z; a1.w += u1.w;
            a2.x += u2.x; a2.y += u2.y; a2.z += u2.z; a2.w += u2.w;
            a3.x += u3.x; a3.y += u3.y; a3.z += u3.z; a3.w += u3.w;
        }
        float4 s = make_float4(a0.x + a1.x + a2.x + a3.x, a0.y + a1.y + a2.y + a3.y,
                               a0.z + a1.z + a2.z + a3.z, a0.w + a1.w + a2.w + a3.w);
        *(float4*)&g_S[b][n0 + tid * 4] = s;
        return;
    }

    // ---- gram role ----
    const int sp = xb >> 1;
    const int wid = tid >> 5, lane = tid & 31;
    const int wm = wid & 3, wn = wid >> 2;
    const unsigned uBase = smem_u32(dsm);
    // byte layout: buf*32768 + {H:0, L:16384}

    float acc[2][8][4];
#pragma unroll
    for (int mi = 0; mi < 2; mi++)
#pragma unroll
        for (int nb = 0; nb < 8; nb++)
#pragma unroll
            for (int q = 0; q < 4; q++) acc[mi][nb][q] = 0.f;

    const int arow = wm * 32 + (lane & 15);
    const int asel = lane >> 4;                       // col16 low bit sel
    const int brow = (lane & 7) + ((lane >> 4) & 1) * 8;
    const int bsel = (lane >> 3) & 1;

    const size_t kb0 = (size_t)sp * KCHUNK_G;
    const int NIT = KCHUNK_G / 64;   // 16

    const int prow = tid >> 3, pc8 = tid & 7;         // staging: row, col16
    float4 pv[8];

    // prologue: chunk 0
#pragma unroll
    for (int q = 0; q < 4; q++) {
        const float* src = x + (size_t)(b * Cc + prow + q * 32) * Nn + kb0 + pc8 * 8;
        pv[2 * q]     = *(const float4*)src;
        pv[2 * q + 1] = *(const float4*)(src + 4);
    }

    for (int it = 0; it < NIT; it++) {
        const unsigned bufo = (unsigned)(it & 1) * 32768u;
#pragma unroll
        for (int q = 0; q < 4; q++) {
            uint4 hq, lq;
            split8(pv[2 * q], pv[2 * q + 1], hq, lq);
            const unsigned o = sw128(prow + q * 32, pc8);
            *(uint4*)(dsm + bufo + o)           = hq;
            *(uint4*)(dsm + bufo + 16384u + o)  = lq;
        }
        __syncthreads();
        if (it + 1 < NIT) {
            const size_t kb = kb0 + (size_t)(it + 1) * 64;
#pragma unroll
            for (int q = 0; q < 4; q++) {
                const float* src = x + (size_t)(b * Cc + prow + q * 32) * Nn + kb + pc8 * 8;
                pv[2 * q]     = *(const float4*)src;
                pv[2 * q + 1] = *(const float4*)(src + 4);
            }
        }

        const unsigned uH = uBase + bufo, uL = uH + 16384u;
#pragma unroll
        for (int kk = 0; kk < 4; kk++) {
            unsigned aH[2][4], aL[2][4];
#pragma unroll
            for (int mi = 0; mi < 2; mi++) {
                const unsigned ao = sw128(arow + mi * 16, kk * 2 + asel);
                ldsm4(aH[mi], uH + ao);
                ldsm4(aL[mi], uL + ao);
            }
#pragma unroll
            for (int ni = 0; ni < 4; ni++) {
                unsigned bH[4], bL[4];
                const unsigned bo = sw128(wn * 64 + ni * 16 + brow, kk * 2 + bsel);
                ldsm4(bH, uH + bo);
                ldsm4(bL, uL + bo);
#pragma unroll
                for (int mi = 0; mi < 2; mi++) {
                    mma16816(acc[mi][2 * ni],     aH[mi], &bH[0]);
                    mma16816(acc[mi][2 * ni],     aH[mi], &bL[0]);
                    mma16816(acc[mi][2 * ni],     aL[mi], &bH[0]);
                    mma16816(acc[mi][2 * ni + 1], aH[mi], &bH[2]);
                    mma16816(acc[mi][2 * ni + 1], aH[mi], &bL[2]);
                    mma16816(acc[mi][2 * ni + 1], aL[mi], &bH[2]);
                }
            }
        }
        // no trailing sync: next STS targets the other buffer; the following
        // sync (next iteration) guarantees this buffer's MMAs finished before
        // it is overwritten two iterations from now.
    }

    float* gp = &g_part[sp][b][0][0];
#pragma unroll
    for (int mi = 0; mi < 2; mi++) {
        const int r0 = wm * 32 + mi * 16 + (lane >> 2);
#pragma unroll
        for (int nb = 0; nb < 8; nb++) {
            const int col = wn * 64 + nb * 8 + (lane & 3) * 2;
            *(float2*)(gp + (size_t)r0 * Cc + col) =
                make_float2(acc[mi][nb][0], acc[mi][nb][1]);
            *(float2*)(gp + (size_t)(r0 + 8) * Cc + col) =
                make_float2(acc[mi][nb][2], acc[mi][nb][3]);
        }
    }
}

// ---------------------------------------------------------------------------
// Kernel 2: reduce split-K partials -> G; row max; bf16 hi/lo of G.
// ---------------------------------------------------------------------------
__global__ __launch_bounds__(128)
void k_reduce() {
    const int c = blockIdx.x, b = blockIdx.y;
    const int d = threadIdx.x;
    float s = 0.f;
#pragma unroll
    for (int sp = 0; sp < SPLITG; sp++) s += g_part[sp][b][c][d];

    float m = s;
#pragma unroll
    for (int o = 16; o; o >>= 1) m = fmaxf(m, __shfl_xor_sync(0xffffffffu, m, o));
    __shared__ float wm[4];
    if ((d & 31) == 0) wm[d >> 5] = m;
    __syncthreads();
    m = fmaxf(fmaxf(wm[0], wm[1]), fmaxf(wm[2], wm[3]));

    __nv_bfloat16 h = __float2bfloat16_rn(s);
    g_Gh[b][c][d] = h;
    g_Gl[b][c][d] = __float2bfloat16_rn(s - __bfloat162float(h));
    if (d == 0) g_m[b][c] = m;
}

// ---------------------------------------------------------------------------
// Kernel 3: att2 = m_c * S[n] - (G*f)[c,n].  A (=G hi/lo) smem-RESIDENT and
// swizzled; B double-buffered; ONE sync per K-chunk.
// dyn smem bytes: Ah[0,32768) Al[32768,65536) B: 65536 + buf*17408 {Bh, Bl+8704}
// ---------------------------------------------------------------------------
__global__ __launch_bounds__(256, 2)
void k_gemm2_mma(const float* __restrict__ x) {
    extern __shared__ __align__(16) char dsm[];
    const int b  = blockIdx.y;
    const int n0 = blockIdx.x * 128;
    const int tid = threadIdx.x;
    const int wid = tid >> 5, lane = tid & 31;
    const int wm = wid & 3, wn = wid >> 2;
    const unsigned uBase = smem_u32(dsm);

    // ---- load resident A = G[b] hi/lo, swizzled 256B rows ----
#pragma unroll
    for (int q = 0; q < 8; q++) {
        const int idx = tid + q * 256;          // 0..2047
        const int row = idx >> 4, col16 = idx & 15;
        const unsigned o = sw256(row, col16);
        *(uint4*)(dsm + o)           = *(const uint4*)&g_Gh[b][row][col16 * 8];
        *(uint4*)(dsm + 32768u + o)  = *(const uint4*)&g_Gl[b][row][col16 * 8];
    }

    float acc[2][8][4];
#pragma unroll
    for (int mi = 0; mi < 2; mi++)
#pragma unroll
        for (int nb = 0; nb < 8; nb++)
#pragma unroll
            for (int q = 0; q < 4; q++) acc[mi][nb][q] = 0.f;

    const int arow = wm * 32 + (lane & 15);
    const int asel = lane >> 4;
    const int btrow = lane & 15;
    const int btcolq = (lane >> 4) * 8;

    const int prow = tid >> 4, pc8 = tid & 15;  // B staging coords
    float4 pB[4];
#pragma unroll
    for (int q = 0; q < 2; q++) {
        const float* src = x + (size_t)(b * Cc + prow + q * 16) * Nn + n0 + pc8 * 8;
        pB[2 * q]     = *(const float4*)src;
        pB[2 * q + 1] = *(const float4*)(src + 4);
    }
    __syncthreads();   // A resident ready

    for (int kt = 0; kt < 4; kt++) {
        const unsigned bOff = 65536u + (unsigned)(kt & 1) * 17408u;
#pragma unroll
        for (int q = 0; q < 2; q++) {
            uint4 hq, lq;
            split8(pB[2 * q], pB[2 * q + 1], hq, lq);
            const unsigned o = (unsigned)((prow + q * 16) * 272 + pc8 * 16);
            *(uint4*)(dsm + bOff + o)          = hq;
            *(uint4*)(dsm + bOff + 8704u + o)  = lq;
        }
        __syncthreads();
        if (kt + 1 < 4) {
            const int k1 = (kt + 1) * 32;
#pragma unroll
            for (int q = 0; q < 2; q++) {
                const float* src =
                    x + (size_t)(b * Cc + k1 + prow + q * 16) * Nn + n0 + pc8 * 8;
                pB[2 * q]     = *(const float4*)src;
                pB[2 * q + 1] = *(const float4*)(src + 4);
            }
        }

        const unsigned uBh = uBase + bOff, uBl = uBh + 8704u;
#pragma unroll
        for (int kk = 0; kk < 2; kk++) {
            unsigned aH[2][4], aL[2][4];
#pragma unroll
            for (int mi = 0; mi < 2; mi++) {
                const unsigned ao = sw256(arow + mi * 16, kt * 4 + kk * 2 + asel);
                ldsm4(aH[mi], uBase + ao);
                ldsm4(aL[mi], uBase + 32768u + ao);
            }
#pragma unroll
            for (int ni = 0; ni < 4; ni++) {
                unsigned bH[4], bL[4];
                const unsigned bo = (unsigned)(
                    (kk * 16 + btrow) * 272 + (wn * 64 + ni * 16 + btcolq) * 2);
                ldsm4t(bH, uBh + bo);
                ldsm4t(bL, uBl + bo);
#pragma unroll
                for (int mi = 0; mi < 2; mi++) {
                    mma16816(acc[mi][2 * ni],     aH[mi], &bH[0]);
                    mma16816(acc[mi][2 * ni],     aH[mi], &bL[0]);
                    mma16816(acc[mi][2 * ni],     aL[mi], &bH[0]);
                    mma16816(acc[mi][2 * ni + 1], aH[mi], &bH[2]);
                    mma16816(acc[mi][2 * ni + 1], aH[mi], &bL[2]);
                    mma16816(acc[mi][2 * ni + 1], aL[mi], &bH[2]);
                }
            }
        }
        // no trailing sync (double-buffered B; A never overwritten)
    }

    // epilogue: att2 = m_c * S[n] - acc
    float* op = g_att2 + (size_t)b * Cc * Nn;
#pragma unroll
    for (int mi = 0; mi < 2; mi++) {
        const int r0 = wm * 32 + mi * 16 + (lane >> 2);
        const float m0 = g_m[b][r0];
        const float m1 = g_m[b][r0 + 8];
#pragma unroll
        for (int nb = 0; nb < 8; nb++) {
            const int col = n0 + wn * 64 + nb * 8 + (lane & 3) * 2;
            const float2 Sv = *(const float2*)&g_S[b][col];
            *(float2*)(op + (size_t)r0 * Nn + col) =
                make_float2(m0 * Sv.x - acc[mi][nb][0],
                            m0 * Sv.y - acc[mi][nb][1]);
            *(float2*)(op + (size_t)(r0 + 8) * Nn + col) =
                make_float2(m1 * Sv.x - acc[mi][nb][2],
                            m1 * Sv.y - acc[mi][nb][3]);
        }
    }
}

// ---------------------------------------------------------------------------
// Kernel 4: depthwise 3x3 conv + bias + softmax(W) + outputs.
// Block = (c, b, quarter): 32 output rows, 34-row halo stage in smem.
// ---------------------------------------------------------------------------
__global__ __launch_bounds__(256)
void k_conv(const float* __restrict__ x, const float* __restrict__ dwW,
            const float* __restrict__ dwB, const float* __restrict__ gamma,
            float* __restrict__ out) {
    __shared__ float sm[34 * 132];
    const int c = blockIdx.x, b = blockIdx.y;
    const int r0 = blockIdx.z * 32;
    const int tid = threadIdx.x;

    for (int i = tid; i < 34 * 132; i += 256) sm[i] = 0.f;
    __syncthreads();

    const float* __restrict__ pl = g_att2 + ((size_t)b * Cc + c) * Nn;
    for (int idx4 = tid; idx4 < 34 * 32; idx4 += 256) {
        const int i = idx4 >> 5, w4 = (idx4 & 31) << 2;
        const int gr = r0 - 1 + i;
        if (gr >= 0 && gr < Hh) {
            float4 u = *(const float4*)(pl + gr * Ww + w4);
            float* rp = sm + i * 132 + 1 + w4;
            rp[0] = u.x; rp[1] = u.y; rp[2] = u.z; rp[3] = u.w;
        }
    }

    float w9[9];
#pragma unroll
    for (int i = 0; i < 9; i++) w9[i] = dwW[c * 9 + i];
    const float bz = dwB[c];
    const float gm = gamma[0];
    __syncthreads();

    const int warp = tid >> 5, lane = tid & 31;
    const float* __restrict__ xp = x + ((size_t)b * Cc + c) * Nn;
    float* __restrict__ op = out + ((size_t)b * Cc + c) * Nn;
    float* __restrict__ ap = out + (size_t)Bb * Cc * Nn + ((size_t)b * Cc + c) * Nn;

    for (int hh = warp; hh < 32; hh += 8) {
        const int h = r0 + hh;
        const int li = hh + 1;
        const int wb = lane << 2;
        float r0v[8], r1v[8], r2v[8];
        {
            float4 a0 = *(const float4*)&sm[(li - 1) * 132 + wb];
            float4 a1 = *(const float4*)&sm[(li - 1) * 132 + wb + 4];
            r0v[0]=a0.x; r0v[1]=a0.y; r0v[2]=a0.z; r0v[3]=a0.w;
            r0v[4]=a1.x; r0v[5]=a1.y; r0v[6]=a1.z; r0v[7]=a1.w;
            float4 b0 = *(const float4*)&sm[(li + 0) * 132 + wb];
            float4 b1 = *(const float4*)&sm[(li + 0) * 132 + wb + 4];
            r1v[0]=b0.x; r1v[1]=b0.y; r1v[2]=b0.z; r1v[3]=b0.w;
            r1v[4]=b1.x; r1v[5]=b1.y; r1v[6]=b1.z; r1v[7]=b1.w;
            float4 c0 = *(const float4*)&sm[(li + 1) * 132 + wb];
            float4 c1 = *(const float4*)&sm[(li + 1) * 132 + wb + 4];
            r2v[0]=c0.x; r2v[1]=c0.y; r2v[2]=c0.z; r2v[3]=c0.w;
            r2v[4]=c1.x; r2v[5]=c1.y; r2v[6]=c1.z; r2v[7]=c1.w;
        }
        float v[4];
#pragma unroll
        for (int j = 0; j < 4; j++) {
            float s = bz;
            s = fmaf(r0v[j],     w9[0], s);
            s = fmaf(r0v[j + 1], w9[1], s);
            s = fmaf(r0v[j + 2], w9[2], s);
            s = fmaf(r1v[j],     w9[3], s);
            s = fmaf(r1v[j + 1], w9[4], s);
            s = fmaf(r1v[j + 2], w9[5], s);
            s = fmaf(r2v[j],     w9[6], s);
            s = fmaf(r2v[j + 1], w9[7], s);
            s = fmaf(r2v[j + 2], w9[8], s);
            v[j] = s;
        }
        float mx = fmaxf(fmaxf(v[0], v[1]), fmaxf(v[2], v[3]));
#pragma unroll
        for (int o = 16; o; o >>= 1) mx = fmaxf(mx, __shfl_xor_sync(0xffffffffu, mx, o));
        float e[4]; float ssum = 0.f;
#pragma unroll
        for (int j = 0; j < 4; j++) { e[j] = __expf(v[j] - mx); ssum += e[j]; }
#pragma unroll
        for (int o = 16; o; o >>= 1) ssum += __shfl_xor_sync(0xffffffffu, ssum, o);
        const float inv = 1.0f / ssum;

        float4 xv = *(const float4*)(xp + h * Ww + wb);
        float4 av = make_float4(e[0] * inv, e[1] * inv, e[2] * inv, e[3] * inv);
        *(float4*)(ap + h * Ww + wb) = av;
        *(float4*)(op + h * Ww + wb) = make_float4(
            fmaf(gm, av.x, xv.x), fmaf(gm, av.y, xv.y),
            fmaf(gm, av.z, xv.z), fmaf(gm, av.w, xv.w));
    }
}

// ---------------------------------------------------------------------------
extern "C" void kernel_launch(void* const* d_in, const int* in_sizes, int n_in,
                              void* d_out, int out_size) {
    (void)in_sizes; (void)n_in; (void)out_size;
    const float* x    = (const float*)d_in[0];
    const float* dwW  = (const float*)d_in[1];
    const float* dwB  = (const float*)d_in[2];
    const float* gm   = (const float*)d_in[3];
    float* out = (float*)d_out;

    cudaFuncSetAttribute(k_gram_sums,
                         cudaFuncAttributeMaxDynamicSharedMemorySize, 65536);
    cudaFuncSetAttribute(k_gemm2_mma,
                         cudaFuncAttributeMaxDynamicSharedMemorySize, 100352);

    k_gram_sums<<<dim3(32, Bb), 256, 65536>>>(x);
    k_reduce   <<<dim3(Cc, Bb), 128>>>();
    k_gemm2_mma<<<dim3(Nn / 128, Bb), 256, 100352>>>(x);
    k_conv     <<<dim3(Cc, Bb, 4), 256>>>(x, dwW, dwB, gm, out);
}

// round 10
// speedup vs baseline: 1.8900x; 1.0291x over previous
#include <cuda_runtime.h>
#include <cuda_bf16.h>

#define Bb 16
#define Cc 128
#define Hh 128
#define Ww 128
#define Nn 16384          // Hh*Ww
#define SPLITG 16         // split-K for Gram
#define KCHUNK_G 1024     // Nn / SPLITG

// ---------------- scratch (static device globals) ----------------
static __device__ float g_part[SPLITG][Bb][Cc][Cc];         // 16 MB Gram split-K partials
static __device__ __nv_bfloat16 g_Gh[Bb][Cc][Cc];           // G hi
static __device__ __nv_bfloat16 g_Gl[Bb][Cc][Cc];           // G lo
static __device__ float g_m[Bb][Cc];                        // row max of G
static __device__ float g_S[Bb][Nn];                        // column sums of f (fp32 exact)
static __device__ float g_att2[(size_t)Bb * Cc * Nn];       // 134 MB pre-conv tensor

// ---------------- mma / ldmatrix helpers (plain PTX, sm_80+) ----------------
__device__ __forceinline__ unsigned smem_u32(const void* p) {
    unsigned a;
    asm("{ .reg .u64 t; cvta.to.shared.u64 t, %1; cvt.u32.u64 %0, t; }"
        : "=r"(a) : "l"(p));
    return a;
}
__device__ __forceinline__ void ldsm4(unsigned* r, unsigned addr) {
    asm volatile("ldmatrix.sync.aligned.m8n8.x4.shared.b16 {%0,%1,%2,%3}, [%4];"
                 : "=r"(r[0]), "=r"(r[1]), "=r"(r[2]), "=r"(r[3]) : "r"(addr));
}
__device__ __forceinline__ void ldsm4t(unsigned* r, unsigned addr) {
    asm volatile("ldmatrix.sync.aligned.m8n8.x4.trans.shared.b16 {%0,%1,%2,%3}, [%4];"
                 : "=r"(r[0]), "=r"(r[1]), "=r"(r[2]), "=r"(r[3]) : "r"(addr));
}
__device__ __forceinline__ void mma16816(float* c, const unsigned* a, const unsigned* b) {
    asm volatile(
        "mma.sync.aligned.m16n8k16.row.col.f32.bf16.bf16.f32 "
        "{%0,%1,%2,%3}, {%4,%5,%6,%7}, {%8,%9}, {%0,%1,%2,%3};"
        : "+f"(c[0]), "+f"(c[1]), "+f"(c[2]), "+f"(c[3])
        : "r"(a[0]), "r"(a[1]), "r"(a[2]), "r"(a[3]), "r"(b[0]), "r"(b[1]));
}

// split 8 fp32 -> 8 bf16 hi + 8 bf16 lo (packed as uint4 each)
__device__ __forceinline__ void split8(const float4 v0, const float4 v1,
                                       uint4& h, uint4& l) {
    __nv_bfloat162 h0 = __floats2bfloat162_rn(v0.x, v0.y);
    __nv_bfloat162 h1 = __floats2bfloat162_rn(v0.z, v0.w);
    __nv_bfloat162 h2 = __floats2bfloat162_rn(v1.x, v1.y);
    __nv_bfloat162 h3 = __floats2bfloat162_rn(v1.z, v1.w);
    unsigned b0 = *(unsigned*)&h0, b1 = *(unsigned*)&h1;
    unsigned b2 = *(unsigned*)&h2, b3 = *(unsigned*)&h3;
    float f0x = __uint_as_float(b0 << 16), f0y = __uint_as_float(b0 & 0xffff0000u);
    float f1x = __uint_as_float(b1 << 16), f1y = __uint_as_float(b1 & 0xffff0000u);
    float f2x = __uint_as_float(b2 << 16), f2y = __uint_as_float(b2 & 0xffff0000u);
    float f3x = __uint_as_float(b3 << 16), f3y = __uint_as_float(b3 & 0xffff0000u);
    __nv_bfloat162 l0 = __floats2bfloat162_rn(v0.x - f0x, v0.y - f0y);
    __nv_bfloat162 l1 = __floats2bfloat162_rn(v0.z - f1x, v0.w - f1y);
    __nv_bfloat162 l2 = __floats2bfloat162_rn(v1.x - f2x, v1.y - f2y);
    __nv_bfloat162 l3 = __floats2bfloat162_rn(v1.z - f3x, v1.w - f3y);
    h = make_uint4(b0, b1, b2, b3);
    l = make_uint4(*(unsigned*)&l0, *(unsigned*)&l1,
                   *(unsigned*)&l2, *(unsigned*)&l3);
}

// swizzled byte offset, 128B rows (gram tiles): row 0..127, col16 0..7
__device__ __forceinline__ unsigned sw128(int row, int col16) {
    return (unsigned)(row * 128 + ((col16 ^ (row & 7)) << 4));
}
// swizzled byte offset, 256B rows (gemm2 resident A): row 0..127, col16 0..15
__device__ __forceinline__ unsigned sw256(int row, int col16) {
    return (unsigned)(row * 256 + ((((col16 ^ row) & 7) | (col16 & 8)) << 4));
}

// ---------------------------------------------------------------------------
// Kernel 1: Gram split-K via HMMA (hi/lo 3-pass) + FUSED exact fp32 column
// sums S (computed from the fp32 prefetch registers before bf16 conversion).
// grid (SPLITG, Bb) = one full wave at 2 CTA/SM.
// dyn smem: [0,65536) tile double-buffer {H,L}; [65536,+16896) sS[2][64][33].
// ---------------------------------------------------------------------------
__global__ __launch_bounds__(256, 2)
void k_gram_mma(const float* __restrict__ x) {
    extern __shared__ __align__(16) char dsm[];
    float* sS = (float*)(dsm + 65536);

    const int b  = blockIdx.y;
    const int sp = blockIdx.x;
    const int tid = threadIdx.x;
    const int wid = tid >> 5, lane = tid & 31;
    const int wm = wid & 3, wn = wid >> 2;
    const unsigned uBase = smem_u32(dsm);

    float acc[2][8][4];
#pragma unroll
    for (int mi = 0; mi < 2; mi++)
#pragma unroll
        for (int nb = 0; nb < 8; nb++)
#pragma unroll
            for (int q = 0; q < 4; q++) acc[mi][nb][q] = 0.f;

    const int arow = wm * 32 + (lane & 15);
    const int asel = lane >> 4;
    const int brow = (lane & 7) + ((lane >> 4) & 1) * 8;
    const int bsel = (lane >> 3) & 1;

    const size_t kb0 = (size_t)sp * KCHUNK_G;
    const int NIT = KCHUNK_G / 64;   // 16

    const int prow = tid >> 3, pc8 = tid & 7;         // staging: row, col16
    float4 pv[8];

    // prologue: chunk 0
#pragma unroll
    for (int q = 0; q < 4; q++) {
        const float* src = x + (size_t)(b * Cc + prow + q * 32) * Nn + kb0 + pc8 * 8;
        pv[2 * q]     = *(const float4*)src;
        pv[2 * q + 1] = *(const float4*)(src + 4);
    }

    for (int it = 0; it < NIT; it++) {
        const unsigned bufo = (unsigned)(it & 1) * 32768u;
        float* sSb = sS + (it & 1) * (64 * 33);
        // exact fp32 column partial sums over this thread's 4 row-groups
        {
            float cs0 = pv[0].x + pv[2].x + pv[4].x + pv[6].x;
            float cs1 = pv[0].y + pv[2].y + pv[4].y + pv[6].y;
            float cs2 = pv[0].z + pv[2].z + pv[4].z + pv[6].z;
            float cs3 = pv[0].w + pv[2].w + pv[4].w + pv[6].w;
            float cs4 = pv[1].x + pv[3].x + pv[5].x + pv[7].x;
            float cs5 = pv[1].y + pv[3].y + pv[5].y + pv[7].y;
            float cs6 = pv[1].z + pv[3].z + pv[5].z + pv[7].z;
            float cs7 = pv[1].w + pv[3].w + pv[5].w + pv[7].w;
            sSb[(pc8 * 8 + 0) * 33 + prow] = cs0;
            sSb[(pc8 * 8 + 1) * 33 + prow] = cs1;
            sSb[(pc8 * 8 + 2) * 33 + prow] = cs2;
            sSb[(pc8 * 8 + 3) * 33 + prow] = cs3;
            sSb[(pc8 * 8 + 4) * 33 + prow] = cs4;
            sSb[(pc8 * 8 + 5) * 33 + prow] = cs5;
            sSb[(pc8 * 8 + 6) * 33 + prow] = cs6;
            sSb[(pc8 * 8 + 7) * 33 + prow] = cs7;
        }
        // convert + store staged tile
#pragma unroll
        for (int q = 0; q < 4; q++) {
            uint4 hq, lq;
            split8(pv[2 * q], pv[2 * q + 1], hq, lq);
            const unsigned o = sw128(prow + q * 32, pc8);
            *(uint4*)(dsm + bufo + o)           = hq;
            *(uint4*)(dsm + bufo + 16384u + o)  = lq;
        }
        __syncthreads();
        // prefetch next chunk (hidden under MMA below)
        if (it + 1 < NIT) {
            const size_t kb = kb0 + (size_t)(it + 1) * 64;
#pragma unroll
            for (int q = 0; q < 4; q++) {
                const float* src = x + (size_t)(b * Cc + prow + q * 32) * Nn + kb + pc8 * 8;
                pv[2 * q]     = *(const float4*)src;
                pv[2 * q + 1] = *(const float4*)(src + 4);
            }
        }
        // finish S reduction for this chunk (threads 0..63, one col each)
        if (tid < 64) {
            float s = 0.f;
#pragma unroll
            for (int i = 0; i < 32; i++) s += sSb[tid * 33 + i];
            g_S[b][kb0 + (size_t)it * 64 + tid] = s;
        }

        const unsigned uH = uBase + bufo, uL = uH + 16384u;
#pragma unroll
        for (int kk = 0; kk < 4; kk++) {
            unsigned aH[2][4], aL[2][4];
#pragma unroll
            for (int mi = 0; mi < 2; mi++) {
                const unsigned ao = sw128(arow + mi * 16, kk * 2 + asel);
                ldsm4(aH[mi], uH + ao);
                ldsm4(aL[mi], uL + ao);
            }
#pragma unroll
            for (int ni = 0; ni < 4; ni++) {
                unsigned bH[4], bL[4];
                const unsigned bo = sw128(wn * 64 + ni * 16 + brow, kk * 2 + bsel);
                ldsm4(bH, uH + bo);
                ldsm4(bL, uL + bo);
#pragma unroll
                for (int mi = 0; mi < 2; mi++) {
                    mma16816(acc[mi][2 * ni],     aH[mi], &bH[0]);
                    mma16816(acc[mi][2 * ni],     aH[mi], &bL[0]);
                    mma16816(acc[mi][2 * ni],     aL[mi], &bH[0]);
                    mma16816(acc[mi][2 * ni + 1], aH[mi], &bH[2]);
                    mma16816(acc[mi][2 * ni + 1], aH[mi], &bL[2]);
                    mma16816(acc[mi][2 * ni + 1], aL[mi], &bH[2]);
                }
            }
        }
        // no trailing sync: tiles and sS are double-buffered; the next
        // iteration's sync orders reuse two iterations out.
    }

    float* gp = &g_part[sp][b][0][0];
#pragma unroll
    for (int mi = 0; mi < 2; mi++) {
        const int r0 = wm * 32 + mi * 16 + (lane >> 2);
#pragma unroll
        for (int nb = 0; nb < 8; nb++) {
            const int col = wn * 64 + nb * 8 + (lane & 3) * 2;
            *(float2*)(gp + (size_t)r0 * Cc + col) =
                make_float2(acc[mi][nb][0], acc[mi][nb][1]);
            *(float2*)(gp + (size_t)(r0 + 8) * Cc + col) =
                make_float2(acc[mi][nb][2], acc[mi][nb][3]);
        }
    }
}

// ---------------------------------------------------------------------------
// Kernel 2: reduce split-K partials -> G; row max; bf16 hi/lo of G.
// ---------------------------------------------------------------------------
__global__ __launch_bounds__(128)
void k_reduce() {
    const int c = blockIdx.x, b = blockIdx.y;
    const int d = threadIdx.x;
    float s = 0.f;
#pragma unroll
    for (int sp = 0; sp < SPLITG; sp++) s += g_part[sp][b][c][d];

    float m = s;
#pragma unroll
    for (int o = 16; o; o >>= 1) m = fmaxf(m, __shfl_xor_sync(0xffffffffu, m, o));
    __shared__ float wm[4];
    if ((d & 31) == 0) wm[d >> 5] = m;
    __syncthreads();
    m = fmaxf(fmaxf(wm[0], wm[1]), fmaxf(wm[2], wm[3]));

    __nv_bfloat16 h = __float2bfloat16_rn(s);
    g_Gh[b][c][d] = h;
    g_Gl[b][c][d] = __float2bfloat16_rn(s - __bfloat162float(h));
    if (d == 0) g_m[b][c] = m;
}

// ---------------------------------------------------------------------------
// Kernel 3: att2 = m_c * S[n] - (G*f)[c,n].  A (=G hi/lo) smem-RESIDENT and
// swizzled; B double-buffered; ONE sync per K-chunk.
// ---------------------------------------------------------------------------
__global__ __launch_bounds__(256, 2)
void k_gemm2_mma(const float* __restrict__ x) {
    extern __shared__ __align__(16) char dsm[];
    const int b  = blockIdx.y;
    const int n0 = blockIdx.x * 128;
    const int tid = threadIdx.x;
    const int wid = tid >> 5, lane = tid & 31;
    const int wm = wid & 3, wn = wid >> 2;
    const unsigned uBase = smem_u32(dsm);

    // ---- load resident A = G[b] hi/lo, swizzled 256B rows ----
#pragma unroll
    for (int q = 0; q < 8; q++) {
        const int idx = tid + q * 256;          // 0..2047
        const int row = idx >> 4, col16 = idx & 15;
        const unsigned o = sw256(row, col16);
        *(uint4*)(dsm + o)           = *(const uint4*)&g_Gh[b][row][col16 * 8];
        *(uint4*)(dsm + 32768u + o)  = *(const uint4*)&g_Gl[b][row][col16 * 8];
    }

    float acc[2][8][4];
#pragma unroll
    for (int mi = 0; mi < 2; mi++)
#pragma unroll
        for (int nb = 0; nb < 8; nb++)
#pragma unroll
            for (int q = 0; q < 4; q++) acc[mi][nb][q] = 0.f;

    const int arow = wm * 32 + (lane & 15);
    const int asel = lane >> 4;
    const int btrow = lane & 15;
    const int btcolq = (lane >> 4) * 8;

    const int prow = tid >> 4, pc8 = tid & 15;  // B staging coords
    float4 pB[4];
#pragma unroll
    for (int q = 0; q < 2; q++) {
        const float* src = x + (size_t)(b * Cc + prow + q * 16) * Nn + n0 + pc8 * 8;
        pB[2 * q]     = *(const float4*)src;
        pB[2 * q + 1] = *(const float4*)(src + 4);
    }
    __syncthreads();   // A resident ready

    for (int kt = 0; kt < 4; kt++) {
        const unsigned bOff = 65536u + (unsigned)(kt & 1) * 17408u;
#pragma unroll
        for (int q = 0; q < 2; q++) {
            uint4 hq, lq;
            split8(pB[2 * q], pB[2 * q + 1], hq, lq);
            const unsigned o = (unsigned)((prow + q * 16) * 272 + pc8 * 16);
            *(uint4*)(dsm + bOff + o)          = hq;
            *(uint4*)(dsm + bOff + 8704u + o)  = lq;
        }
        __syncthreads();
        if (kt + 1 < 4) {
            const int k1 = (kt + 1) * 32;
#pragma unroll
            for (int q = 0; q < 2; q++) {
                const float* src =
                    x + (size_t)(b * Cc + k1 + prow + q * 16) * Nn + n0 + pc8 * 8;
                pB[2 * q]     = *(const float4*)src;
                pB[2 * q + 1] = *(const float4*)(src + 4);
            }
        }

        const unsigned uBh = uBase + bOff, uBl = uBh + 8704u;
#pragma unroll
        for (int kk = 0; kk < 2; kk++) {
            unsigned aH[2][4], aL[2][4];
#pragma unroll
            for (int mi = 0; mi < 2; mi++) {
                const unsigned ao = sw256(arow + mi * 16, kt * 4 + kk * 2 + asel);
                ldsm4(aH[mi], uBase + ao);
                ldsm4(aL[mi], uBase + 32768u + ao);
            }
#pragma unroll
            for (int ni = 0; ni < 4; ni++) {
                unsigned bH[4], bL[4];
                const unsigned bo = (unsigned)(
                    (kk * 16 + btrow) * 272 + (wn * 64 + ni * 16 + btcolq) * 2);
                ldsm4t(bH, uBh + bo);
                ldsm4t(bL, uBl + bo);
#pragma unroll
                for (int mi = 0; mi < 2; mi++) {
                    mma16816(acc[mi][2 * ni],     aH[mi], &bH[0]);
                    mma16816(acc[mi][2 * ni],     aH[mi], &bL[0]);
                    mma16816(acc[mi][2 * ni],     aL[mi], &bH[0]);
                    mma16816(acc[mi][2 * ni + 1], aH[mi], &bH[2]);
                    mma16816(acc[mi][2 * ni + 1], aH[mi], &bL[2]);
                    mma16816(acc[mi][2 * ni + 1], aL[mi], &bH[2]);
                }
            }
        }
    }

    // epilogue: att2 = m_c * S[n] - acc
    float* op = g_att2 + (size_t)b * Cc * Nn;
#pragma unroll
    for (int mi = 0; mi < 2; mi++) {
        const int r0 = wm * 32 + mi * 16 + (lane >> 2);
        const float m0 = g_m[b][r0];
        const float m1 = g_m[b][r0 + 8];
#pragma unroll
        for (int nb = 0; nb < 8; nb++) {
            const int col = n0 + wn * 64 + nb * 8 + (lane & 3) * 2;
            const float2 Sv = *(const float2*)&g_S[b][col];
            *(float2*)(op + (size_t)r0 * Nn + col) =
                make_float2(m0 * Sv.x - acc[mi][nb][0],
                            m0 * Sv.y - acc[mi][nb][1]);
            *(float2*)(op + (size_t)(r0 + 8) * Nn + col) =
                make_float2(m1 * Sv.x - acc[mi][nb][2],
                            m1 * Sv.y - acc[mi][nb][3]);
        }
    }
}

// ---------------------------------------------------------------------------
// Kernel 4: depthwise 3x3 conv + bias + softmax(W) + outputs.
// Block = (c, b, quarter): 32 output rows, 34-row halo stage in smem.
// Streaming loads/stores (single-use data).
// ---------------------------------------------------------------------------
__global__ __launch_bounds__(256)
void k_conv(const float* __restrict__ x, const float* __restrict__ dwW,
            const float* __restrict__ dwB, const float* __restrict__ gamma,
            float* __restrict__ out) {
    __shared__ float sm[34 * 132];
    const int c = blockIdx.x, b = blockIdx.y;
    const int r0 = blockIdx.z * 32;
    const int tid = threadIdx.x;

    for (int i = tid; i < 34 * 132; i += 256) sm[i] = 0.f;
    __syncthreads();

    const float* __restrict__ pl = g_att2 + ((size_t)b * Cc + c) * Nn;
    for (int idx4 = tid; idx4 < 34 * 32; idx4 += 256) {
        const int i = idx4 >> 5, w4 = (idx4 & 31) << 2;
        const int gr = r0 - 1 + i;
        if (gr >= 0 && gr < Hh) {
            float4 u = __ldcs((const float4*)(pl + gr * Ww + w4));
            float* rp = sm + i * 132 + 1 + w4;
            rp[0] = u.x; rp[1] = u.y; rp[2] = u.z; rp[3] = u.w;
        }
    }

    float w9[9];
#pragma unroll
    for (int i = 0; i < 9; i++) w9[i] = dwW[c * 9 + i];
    const float bz = dwB[c];
    const float gm = gamma[0];
    __syncthreads();

    const int warp = tid >> 5, lane = tid & 31;
    const float* __restrict__ xp = x + ((size_t)b * Cc + c) * Nn;
    float* __restrict__ op = out + ((size_t)b * Cc + c) * Nn;
    float* __restrict__ ap = out + (size_t)Bb * Cc * Nn + ((size_t)b * Cc + c) * Nn;

    for (int hh = warp; hh < 32; hh += 8) {
        const int h = r0 + hh;
        const int li = hh + 1;
        const int wb = lane << 2;
        float r0v[8], r1v[8], r2v[8];
        {
            float4 a0 = *(const float4*)&sm[(li - 1) * 132 + wb];
            float4 a1 = *(const float4*)&sm[(li - 1) * 132 + wb + 4];
            r0v[0]=a0.x; r0v[1]=a0.y; r0v[2]=a0.z; r0v[3]=a0.w;
            r0v[4]=a1.x; r0v[5]=a1.y; r0v[6]=a1.z; r0v[7]=a1.w;
            float4 b0 = *(const float4*)&sm[(li + 0) * 132 + wb];
            float4 b1 = *(const float4*)&sm[(li + 0) * 132 + wb + 4];
            r1v[0]=b0.x; r1v[1]=b0.y; r1v[2]=b0.z; r1v[3]=b0.w;
            r1v[4]=b1.x; r1v[5]=b1.y; r1v[6]=b1.z; r1v[7]=b1.w;
            float4 c0 = *(const float4*)&sm[(li + 1) * 132 + wb];
            float4 c1 = *(const float4*)&sm[(li + 1) * 132 + wb + 4];
            r2v[0]=c0.x; r2v[1]=c0.y; r2v[2]=c0.z; r2v[3]=c0.w;
            r2v[4]=c1.x; r2v[5]=c1.y; r2v[6]=c1.z; r2v[7]=c1.w;
        }
        float v[4];
#pragma unroll
        for (int j = 0; j < 4; j++) {
            float s = bz;
            s = fmaf(r0v[j],     w9[0], s);
            s = fmaf(r0v[j + 1], w9[1], s);
            s = fmaf(r0v[j + 2], w9[2], s);
            s = fmaf(r1v[j],     w9[3], s);
            s = fmaf(r1v[j + 1], w9[4], s);
            s = fmaf(r1v[j + 2], w9[5], s);
            s = fmaf(r2v[j],     w9[6], s);
            s = fmaf(r2v[j + 1], w9[7], s);
            s = fmaf(r2v[j + 2], w9[8], s);
            v[j] = s;
        }
        float mx = fmaxf(fmaxf(v[0], v[1]), fmaxf(v[2], v[3]));
#pragma unroll
        for (int o = 16; o; o >>= 1) mx = fmaxf(mx, __shfl_xor_sync(0xffffffffu, mx, o));
        float e[4]; float ssum = 0.f;
#pragma unroll
        for (int j = 0; j < 4; j++) { e[j] = __expf(v[j] - mx); ssum += e[j]; }
#pragma unroll
        for (int o = 16; o; o >>= 1) ssum += __shfl_xor_sync(0xffffffffu, ssum, o);
        const float inv = 1.0f / ssum;

        float4 xv = __ldcs((const float4*)(xp + h * Ww + wb));
        float4 av = make_float4(e[0] * inv, e[1] * inv, e[2] * inv, e[3] * inv);
        __stcs((float4*)(ap + h * Ww + wb), av);
        __stcs((float4*)(op + h * Ww + wb), make_float4(
            fmaf(gm, av.x, xv.x), fmaf(gm, av.y, xv.y),
            fmaf(gm, av.z, xv.z), fmaf(gm, av.w, xv.w)));
    }
}

// ---------------------------------------------------------------------------
extern "C" void kernel_launch(void* const* d_in, const int* in_sizes, int n_in,
                              void* d_out, int out_size) {
    (void)in_sizes; (void)n_in; (void)out_size;
    const float* x    = (const float*)d_in[0];
    const float* dwW  = (const float*)d_in[1];
    const float* dwB  = (const float*)d_in[2];
    const float* gm   = (const float*)d_in[3];
    float* out = (float*)d_out;

    cudaFuncSetAttribute(k_gram_mma,
                         cudaFuncAttributeMaxDynamicSharedMemorySize, 82432);
    cudaFuncSetAttribute(k_gemm2_mma,
                         cudaFuncAttributeMaxDynamicSharedMemorySize, 100352);

    k_gram_mma <<<dim3(SPLITG, Bb), 256, 82432>>>(x);
    k_reduce   <<<dim3(Cc, Bb), 128>>>();
    k_gemm2_mma<<<dim3(Nn / 128, Bb), 256, 100352>>>(x);
    k_conv     <<<dim3(Cc, Bb, 4), 256>>>(x, dwW, dwB, gm, out);
}